// round 5
// baseline (speedup 1.0000x reference)
#include <cuda_runtime.h>
#include <math.h>
#include <stdint.h>

#define N_RNA 4096
#define N_ATAC 8192
#define IN_C 256
#define HID 128
#define THR_S 0.8f

// ---------------- scratch (static device memory; no allocations) ----------------
__device__ float g_Q[N_RNA * HID];
__device__ float g_K[N_ATAC * HID];
__device__ float g_VR[N_RNA * HID];
__device__ float g_VA[N_ATAC * HID];
__device__ float g_AGGR[N_RNA * HID];
__device__ float g_AGGA[N_ATAC * HID];
__device__ float g_CR[N_RNA * 2 * HID];
__device__ float g_CA[N_ATAC * 2 * HID];

// ---------------- batched GEMM (unchanged, known-good) ----------------
struct GemmOp {
    const float* A;
    const float* W;
    const float* B;
    float* C;
    int M;
    int K;
    int ldc;
    int coff;
};
struct GemmBatch { GemmOp op[6]; };

__global__ void __launch_bounds__(256) gemm_kernel(GemmBatch batch) {
    const GemmOp op = batch.op[blockIdx.y];
    const int m0 = blockIdx.x * 64;
    if (m0 >= op.M) return;

    __shared__ float a_s[64][33];
    __shared__ float w_s[32][128];

    float acc[8][4];
#pragma unroll
    for (int i = 0; i < 8; ++i) {
        acc[i][0] = 0.f; acc[i][1] = 0.f; acc[i][2] = 0.f; acc[i][3] = 0.f;
    }

    const int t = threadIdx.x;
    const float4* A4 = (const float4*)op.A;
    const float4* W4 = (const float4*)op.W;
    const int Kd4 = op.K >> 2;

    for (int kk = 0; kk < op.K; kk += 32) {
        __syncthreads();
        {
            int k4 = t & 7, r = t >> 3;
#pragma unroll
            for (int rr = 0; rr < 2; ++rr) {
                float4 v = A4[(size_t)(m0 + r + rr * 32) * Kd4 + (kk >> 2) + k4];
                a_s[r + rr * 32][k4 * 4 + 0] = v.x;
                a_s[r + rr * 32][k4 * 4 + 1] = v.y;
                a_s[r + rr * 32][k4 * 4 + 2] = v.z;
                a_s[r + rr * 32][k4 * 4 + 3] = v.w;
            }
        }
        {
#pragma unroll
            for (int p = 0; p < 4; ++p) {
                int idx = t + p * 256;
                int k = idx >> 5, c4 = idx & 31;
                *(float4*)&w_s[k][c4 * 4] = W4[(size_t)(kk + k) * 32 + c4];
            }
        }
        __syncthreads();
#pragma unroll
        for (int k = 0; k < 32; ++k) {
            float4 w4 = *(const float4*)&w_s[k][(t & 31) * 4];
#pragma unroll
            for (int i = 0; i < 8; ++i) {
                float av = a_s[(t >> 5) * 8 + i][k];
                acc[i][0] += av * w4.x;
                acc[i][1] += av * w4.y;
                acc[i][2] += av * w4.z;
                acc[i][3] += av * w4.w;
            }
        }
    }

    const int c = (t & 31) * 4;
    const int rb = (t >> 5) * 8;
    float4 b4 = *(const float4*)&op.B[c];
#pragma unroll
    for (int i = 0; i < 8; ++i) {
        size_t row = (size_t)(m0 + rb + i);
        float4 o;
        o.x = acc[i][0] + b4.x;
        o.y = acc[i][1] + b4.y;
        o.z = acc[i][2] + b4.z;
        o.w = acc[i][3] + b4.w;
        *(float4*)&op.C[row * op.ldc + op.coff + c] = o;
    }
}

// ---------------- packed f32x2 helpers ----------------
typedef unsigned long long u64;

__device__ __forceinline__ u64 fma2(u64 a, u64 b, u64 c) {
    u64 d;
    asm("fma.rn.f32x2 %0, %1, %2, %3;" : "=l"(d) : "l"(a), "l"(b), "l"(c));
    return d;
}
__device__ __forceinline__ u64 pack2(float lo, float hi) {
    u64 r;
    asm("mov.b64 %0, {%1, %2};" : "=l"(r) : "f"(lo), "f"(hi));
    return r;
}
__device__ __forceinline__ void unpack2(u64 v, float& lo, float& hi) {
    asm("mov.b64 {%0, %1}, %2;" : "=f"(lo), "=f"(hi) : "l"(v));
}

// ---------------- top-k helpers ----------------
__device__ __forceinline__ bool tk_better(float v, int i, float v2, int i2) {
    return (v > v2) || (v == v2 && i < i2);
}

// full-comparator insert (merge phase)
__device__ __forceinline__ void tk_insert(float* bv, int* bi, float v, int gi) {
    bool done = false;
#pragma unroll
    for (int k = 9; k > 0; --k) {
        if (!done) {
            if (tk_better(v, gi, bv[k - 1], bi[k - 1])) {
                bv[k] = bv[k - 1];
                bi[k] = bi[k - 1];
            } else {
                bv[k] = v;
                bi[k] = gi;
                done = true;
            }
        }
    }
    if (!done) { bv[0] = v; bi[0] = gi; }
}

// value-only insert: candidates arrive in ascending index order
// (ties lose to the already-present lower index -> strict >)
__device__ __forceinline__ void tk_insert_v(float* bv, int* bi, float v, int gi) {
    bool done = false;
#pragma unroll
    for (int k = 9; k > 0; --k) {
        if (!done) {
            if (v > bv[k - 1]) {
                bv[k] = bv[k - 1];
                bi[k] = bi[k - 1];
            } else {
                bv[k] = v;
                bi[k] = gi;
                done = true;
            }
        }
    }
    if (!done) { bv[0] = v; bi[0] = gi; }
}

// ---------------- fused attention v4: f32x2 FMA, broadcast LDS, in-reg top-k ----------------
// Block: 16 rna rows x 2 heads, a streamed in 128-wide chunks (64 chunks).
// Lane map: ag_low = t&3, hh = (t>>2)&1, rg = (t>>3)&3, ag = ag_low + (t>>5)*4.
// Per thread: 4 rows (rg*4+i) x 8 a (ag + jj*16 and +64) of one head; acc packed f32x2 over a.
//
// Smem (91072 B -> 2 blocks/SM):
//   q2 : float4[2][32 dpair][16 r]   {q_d0,q_d0,q_d1,q_d1}, head-padded   @0      (16448 B)
//   k_s: float4[2][16 dd][129 a]     d4-major over d, head-padded         @16448  (66176 B)
//   m_s: float [16][132]                                                  @82624  (8448 B)
// top-k merge buffers overlay k_s after the main loop.
#define SM_Q2 0
#define SM_K  16448
#define SM_M  82624
#define SM_TOTAL 91072
#define QH 514    // float4 stride between heads in q2 (32*16 + 2 pad)
#define KH 2068   // float4 stride between heads in k_s (16*129 + 4 pad)
#define NCHUNK (N_ATAC / 128)

__global__ void __launch_bounds__(128) attn_kernel(const float* __restrict__ mask) {
    extern __shared__ char smraw[];
    float4* const q2 = (float4*)(smraw + SM_Q2);
    float4* const k_s = (float4*)(smraw + SM_K);
    float* const m_s = (float*)(smraw + SM_M);

    const int t = threadIdx.x;
    const int r0 = blockIdx.x * 16;

    const int hh = (t >> 2) & 1;
    const int rg = (t >> 3) & 3;
    const int ag = (t & 3) + (t >> 5) * 4;   // 0..15

    const float4* Q4 = (const float4*)g_Q;
    const float4* K4 = (const float4*)g_K;
    const float4* M4 = (const float4*)mask;

    // staging lanes (coalesced LDG, 4-way-floor STS)
    const int sd4 = t & 31;
    const int shh = sd4 >> 4, sdd = sd4 & 15;
    const int sal = t >> 5;

    // ---- build q2 (pre-splatted Q) ----
    {
#pragma unroll
        for (int j = 0; j < 4; ++j) {
            int r = (t >> 5) + j * 4;   // 0..15
            float4 v = Q4[(size_t)(r0 + r) * 32 + sd4];
            q2[shh * QH + (2 * sdd) * 16 + r] = make_float4(v.x, v.x, v.y, v.y);
            q2[shh * QH + (2 * sdd + 1) * 16 + r] = make_float4(v.z, v.z, v.w, v.w);
        }
    }

    // per-thread 4 per-row top-10 lists (flat, compile-time indexed)
    float bv[40];
    int bi[40];
#pragma unroll
    for (int k = 0; k < 40; ++k) { bv[k] = -1e30f; bi[k] = 0x7fffffff; }

    for (int c = 0; c < NCHUNK; ++c) {
        const int a0 = c * 128;

        __syncthreads();   // previous compute done reading k_s/m_s (and q2 ready, c==0)

        // ---- stage K chunk: coalesced LDG -> padded d4-major STS ----
#pragma unroll 8
        for (int j = 0; j < 32; ++j) {
            int a = sal + j * 4;
            float4 v = K4[(size_t)(a0 + a) * 32 + sd4];
            k_s[shh * KH + sdd * 129 + a] = v;
        }
        // ---- stage mask tile [16][132] ----
#pragma unroll
        for (int p = 0; p < 4; ++p) {
            int e = t + 128 * p;
            int row = e >> 5, c4 = e & 31;
            *(float4*)&m_s[row * 132 + c4 * 4] =
                M4[(size_t)(r0 + row) * 2048 + (a0 >> 2) + c4];
        }
        __syncthreads();

        // ---- packed logits: acc2[i][jj] = f32x2 over (a, a+64) ----
        u64 acc2[4][4];
#pragma unroll
        for (int i = 0; i < 4; ++i)
#pragma unroll
            for (int jj = 0; jj < 4; ++jj) acc2[i][jj] = 0ull;

#pragma unroll
        for (int dd = 0; dd < 16; ++dd) {
            const int kbase = hh * KH + dd * 129 + ag;
            float4 kf[8];
#pragma unroll
            for (int j = 0; j < 8; ++j) kf[j] = k_s[kbase + j * 16];

            u64 kp[4][4];
#pragma unroll
            for (int jj = 0; jj < 4; ++jj) {
                kp[jj][0] = pack2(kf[jj].x, kf[jj + 4].x);
                kp[jj][1] = pack2(kf[jj].y, kf[jj + 4].y);
                kp[jj][2] = pack2(kf[jj].z, kf[jj + 4].z);
                kp[jj][3] = pack2(kf[jj].w, kf[jj + 4].w);
            }

            const int qbase = hh * QH + (2 * dd) * 16 + rg * 4;
#pragma unroll
            for (int i = 0; i < 4; ++i) {
                ulonglong2 qa = *(const ulonglong2*)&q2[qbase + i];        // splat d0,d1
                ulonglong2 qb = *(const ulonglong2*)&q2[qbase + 16 + i];   // splat d2,d3
#pragma unroll
                for (int jj = 0; jj < 4; ++jj) {
                    acc2[i][jj] = fma2(kp[jj][0], qa.x, acc2[i][jj]);
                    acc2[i][jj] = fma2(kp[jj][1], qa.y, acc2[i][jj]);
                    acc2[i][jj] = fma2(kp[jj][2], qb.x, acc2[i][jj]);
                    acc2[i][jj] = fma2(kp[jj][3], qb.y, acc2[i][jj]);
                }
            }
        }

        // ---- mask + in-register top-k filter (sigmoid monotone -> rank on logits) ----
#pragma unroll
        for (int i = 0; i < 4; ++i) {
            const int r = rg * 4 + i;
            const float* mrow = m_s + r * 132;
            float v[8];
#pragma unroll
            for (int jj = 0; jj < 4; ++jj) {
                float lo, hi;
                unpack2(acc2[i][jj], lo, hi);
                v[jj] = lo * mrow[ag + jj * 16];
                v[4 + jj] = hi * mrow[ag + jj * 16 + 64];
            }
            float mx = fmaxf(fmaxf(fmaxf(v[0], v[1]), fmaxf(v[2], v[3])),
                             fmaxf(fmaxf(v[4], v[5]), fmaxf(v[6], v[7])));
            if (mx > bv[i * 10 + 9]) {
                // ascending a: jj lo (ag+jj*16) then jj hi (+64)
#pragma unroll
                for (int idx = 0; idx < 8; ++idx) {
                    int a_g = a0 + ag + (idx & 3) * 16 + (idx >> 2) * 64;
                    if (v[idx] > bv[i * 10 + 9])
                        tk_insert_v(bv + i * 10, bi + i * 10, v[idx], a_g);
                }
            }
        }
    }

    __syncthreads();   // all chunks done; k_s dead -> overlay

    float* tv = (float*)(smraw + SM_K);     // [32 rows][16 lists][10]  (20480 B)
    int* ti = (int*)(tv + 5120);            // (20480 B)
    float* wv = (float*)(ti + 5120);        // [32*10]
    int* wi = (int*)(wv + 320);             // [32*10]

#pragma unroll
    for (int i = 0; i < 4; ++i) {
        int ri = (rg * 4 + i) * 2 + hh;
#pragma unroll
        for (int k = 0; k < 10; ++k) {
            tv[(ri * 16 + ag) * 10 + k] = bv[i * 10 + k];
            ti[(ri * 16 + ag) * 10 + k] = bi[i * 10 + k];
        }
    }
    __syncthreads();

    // merge 16 partial lists per row -> sigmoid/softmax/threshold weights
    if (t < 32) {
        float fv[10];
        int fi[10];
#pragma unroll
        for (int k = 0; k < 10; ++k) { fv[k] = -1e30f; fi[k] = 0x7fffffff; }
        for (int s = 0; s < 16; ++s)
            for (int k = 0; k < 10; ++k) {
                float v = tv[(t * 16 + s) * 10 + k];
                int gi = ti[(t * 16 + s) * 10 + k];
                if (tk_better(v, gi, fv[9], fi[9])) tk_insert(fv, fi, v, gi);
            }
        float sig[10];
#pragma unroll
        for (int k = 0; k < 10; ++k) sig[k] = 1.f / (1.f + expf(-fv[k]));
        float e[10];
        float den = 0.f;
#pragma unroll
        for (int k = 0; k < 10; ++k) { e[k] = expf(sig[k] - sig[0]); den += e[k]; }
        float inv = 1.f / den;
#pragma unroll
        for (int k = 0; k < 10; ++k) {
            float w = e[k] * inv;
            if (!(sig[k] > THR_S)) w = 0.f;
            wv[t * 10 + k] = w;
            wi[t * 10 + k] = fi[k];
        }
    }
    __syncthreads();

    // sparse aggregation: rna gather (direct) + atac scatter (atomic)
    {
        int d = t & 63, g = t >> 6;
        for (int rr = g; rr < 32; rr += 2) {
            int rloc = rr >> 1, h = rr & 1;
            int r = r0 + rloc;
            float vr = g_VR[(size_t)r * 128 + h * 64 + d];
            float accO = 0.f;
#pragma unroll
            for (int k = 0; k < 10; ++k) {
                float w = wv[rr * 10 + k];
                int a = wi[rr * 10 + k];
                if (w != 0.f) {
                    accO += w * g_VA[(size_t)a * 128 + h * 64 + d];
                    atomicAdd(&g_AGGA[(size_t)a * 128 + h * 64 + d], w * vr);
                }
            }
            g_AGGR[(size_t)r * 128 + h * 64 + d] = accO;
        }
    }
}

// ---------------- launch ----------------
extern "C" void kernel_launch(void* const* d_in, const int* in_sizes, int n_in,
                              void* d_out, int out_size) {
    const float* x_rna = (const float*)d_in[0];
    const float* x_atac = (const float*)d_in[1];
    const float* chrom_mask = (const float*)d_in[2];
    const float* Wq = (const float*)d_in[3];
    const float* bq = (const float*)d_in[4];
    const float* Wk = (const float*)d_in[5];
    const float* bk = (const float*)d_in[6];
    const float* Wvr = (const float*)d_in[7];
    const float* bvr = (const float*)d_in[8];
    const float* Wva = (const float*)d_in[9];
    const float* bva = (const float*)d_in[10];
    const float* Wor = (const float*)d_in[11];
    const float* bor = (const float*)d_in[12];
    const float* Woa = (const float*)d_in[13];
    const float* boa = (const float*)d_in[14];
    const float* Wsr = (const float*)d_in[15];
    const float* bsr = (const float*)d_in[16];
    const float* Wsa = (const float*)d_in[17];
    const float* bsa = (const float*)d_in[18];
    const float* Wdr = (const float*)d_in[19];
    const float* bdr = (const float*)d_in[20];
    const float* Wda = (const float*)d_in[21];
    const float* bda = (const float*)d_in[22];
    float* out = (float*)d_out;

    float *Qp, *Kp, *VRp, *VAp, *AGGRp, *AGGAp, *CRp, *CAp;
    cudaGetSymbolAddress((void**)&Qp, g_Q);
    cudaGetSymbolAddress((void**)&Kp, g_K);
    cudaGetSymbolAddress((void**)&VRp, g_VR);
    cudaGetSymbolAddress((void**)&VAp, g_VA);
    cudaGetSymbolAddress((void**)&AGGRp, g_AGGR);
    cudaGetSymbolAddress((void**)&AGGAp, g_AGGA);
    cudaGetSymbolAddress((void**)&CRp, g_CR);
    cudaGetSymbolAddress((void**)&CAp, g_CA);

    cudaMemsetAsync(AGGAp, 0, (size_t)N_ATAC * HID * sizeof(float));

    GemmBatch b1 = {};
    b1.op[0] = {x_rna, Wq, bq, Qp, N_RNA, IN_C, 128, 0};
    b1.op[1] = {x_atac, Wk, bk, Kp, N_ATAC, IN_C, 128, 0};
    b1.op[2] = {x_rna, Wvr, bvr, VRp, N_RNA, IN_C, 128, 0};
    b1.op[3] = {x_atac, Wva, bva, VAp, N_ATAC, IN_C, 128, 0};
    b1.op[4] = {x_rna, Wsr, bsr, CRp, N_RNA, IN_C, 256, 128};
    b1.op[5] = {x_atac, Wsa, bsa, CAp, N_ATAC, IN_C, 256, 128};
    gemm_kernel<<<dim3(128, 6), 256>>>(b1);

    cudaFuncSetAttribute(attn_kernel, cudaFuncAttributeMaxDynamicSharedMemorySize, SM_TOTAL);
    attn_kernel<<<N_RNA / 16, 128, SM_TOTAL>>>(chrom_mask);

    GemmBatch b2 = {};
    b2.op[0] = {AGGRp, Wor, bor, CRp, N_RNA, HID, 256, 0};
    b2.op[1] = {AGGAp, Woa, boa, CAp, N_ATAC, HID, 256, 0};
    gemm_kernel<<<dim3(128, 2), 256>>>(b2);

    GemmBatch b3 = {};
    b3.op[0] = {CRp, Wdr, bdr, out, N_RNA, 2 * HID, 128, 0};
    b3.op[1] = {CAp, Wda, bda, out + (size_t)N_RNA * HID, N_ATAC, 2 * HID, 128, 0};
    gemm_kernel<<<dim3(128, 2), 256>>>(b3);
}

// round 6
// speedup vs baseline: 1.1023x; 1.1023x over previous
#include <cuda_runtime.h>
#include <math.h>
#include <stdint.h>

#define N_RNA 4096
#define N_ATAC 8192
#define IN_C 256
#define HID 128
#define THR_S 0.8f

// ---------------- scratch (static device memory; no allocations) ----------------
__device__ float g_Q[N_RNA * HID];
__device__ float g_K[N_ATAC * HID];
__device__ float g_VR[N_RNA * HID];
__device__ float g_VA[N_ATAC * HID];
__device__ float g_AGGR[N_RNA * HID];
__device__ float g_AGGA[N_ATAC * HID];
__device__ float g_CR[N_RNA * 2 * HID];
__device__ float g_CA[N_ATAC * 2 * HID];

// ---------------- batched GEMM (unchanged, known-good) ----------------
struct GemmOp {
    const float* A;
    const float* W;
    const float* B;
    float* C;
    int M;
    int K;
    int ldc;
    int coff;
};
struct GemmBatch { GemmOp op[6]; };

__global__ void __launch_bounds__(256) gemm_kernel(GemmBatch batch) {
    const GemmOp op = batch.op[blockIdx.y];
    const int m0 = blockIdx.x * 64;
    if (m0 >= op.M) return;

    __shared__ float a_s[64][33];
    __shared__ float w_s[32][128];

    float acc[8][4];
#pragma unroll
    for (int i = 0; i < 8; ++i) {
        acc[i][0] = 0.f; acc[i][1] = 0.f; acc[i][2] = 0.f; acc[i][3] = 0.f;
    }

    const int t = threadIdx.x;
    const float4* A4 = (const float4*)op.A;
    const float4* W4 = (const float4*)op.W;
    const int Kd4 = op.K >> 2;

    for (int kk = 0; kk < op.K; kk += 32) {
        __syncthreads();
        {
            int k4 = t & 7, r = t >> 3;
#pragma unroll
            for (int rr = 0; rr < 2; ++rr) {
                float4 v = A4[(size_t)(m0 + r + rr * 32) * Kd4 + (kk >> 2) + k4];
                a_s[r + rr * 32][k4 * 4 + 0] = v.x;
                a_s[r + rr * 32][k4 * 4 + 1] = v.y;
                a_s[r + rr * 32][k4 * 4 + 2] = v.z;
                a_s[r + rr * 32][k4 * 4 + 3] = v.w;
            }
        }
        {
#pragma unroll
            for (int p = 0; p < 4; ++p) {
                int idx = t + p * 256;
                int k = idx >> 5, c4 = idx & 31;
                *(float4*)&w_s[k][c4 * 4] = W4[(size_t)(kk + k) * 32 + c4];
            }
        }
        __syncthreads();
#pragma unroll
        for (int k = 0; k < 32; ++k) {
            float4 w4 = *(const float4*)&w_s[k][(t & 31) * 4];
#pragma unroll
            for (int i = 0; i < 8; ++i) {
                float av = a_s[(t >> 5) * 8 + i][k];
                acc[i][0] += av * w4.x;
                acc[i][1] += av * w4.y;
                acc[i][2] += av * w4.z;
                acc[i][3] += av * w4.w;
            }
        }
    }

    const int c = (t & 31) * 4;
    const int rb = (t >> 5) * 8;
    float4 b4 = *(const float4*)&op.B[c];
#pragma unroll
    for (int i = 0; i < 8; ++i) {
        size_t row = (size_t)(m0 + rb + i);
        float4 o;
        o.x = acc[i][0] + b4.x;
        o.y = acc[i][1] + b4.y;
        o.z = acc[i][2] + b4.z;
        o.w = acc[i][3] + b4.w;
        *(float4*)&op.C[row * op.ldc + op.coff + c] = o;
    }
}

// ---------------- top-k helpers ----------------
__device__ __forceinline__ bool tk_better(float v, int i, float v2, int i2) {
    // jax top_k order: larger value first, ties -> lower index first
    return (v > v2) || (v == v2 && i < i2);
}

__device__ __forceinline__ void tk_insert(float* bv, int* bi, float v, int gi) {
    bool done = false;
#pragma unroll
    for (int k = 9; k > 0; --k) {
        if (!done) {
            if (tk_better(v, gi, bv[k - 1], bi[k - 1])) {
                bv[k] = bv[k - 1];
                bi[k] = bi[k - 1];
            } else {
                bv[k] = v;
                bi[k] = gi;
                done = true;
            }
        }
    }
    if (!done) { bv[0] = v; bi[0] = gi; }
}

// ---------------- fused attention v5: 256 threads (4 warps/SMSP), broadcast LDS ----------------
// Block: 16 rna rows x 2 heads, a streamed in 128-wide chunks (64 chunks), grid 256.
// Lane map (t = thread):
//   ag = t & 15        a-lane: a = ag + j*16
//   rp = (t>>4) & 1    row-pair within warp (varies inside warp -> kf/qf broadcast)
//   hh = (t>>5) & 1    head (fixed per warp)
//   rg = t >> 6        row-group 0..3 (fixed per warp)
// Thread computes rows {rg*4 + rp*2 + i | i=0,1}, head hh, 8 a-values. acc[2][8].
//
// Smem 99456 B -> 2 blocks/SM -> 16 warps/SM = 4 per SMSP:
//   q_s : float4[32 d4][17]   @ 0      (8704 B)
//   k_s : float4[32 d4][129]  @ 8704   (66048 B)
//   m_s : float [16][128]     @ 74752  (8192 B)
//   l_s : float [32][129]     @ 82944  (16512 B)
// top-k merge buffers overlay k_s after the main loop.

__global__ void __launch_bounds__(256, 2) attn_kernel(const float* __restrict__ mask) {
    extern __shared__ char smraw[];
    float4* const q_s = (float4*)smraw;                              // [32][17]
    float4* const k_s = (float4*)(smraw + 8704);                     // [32][129]
    float* const m_s = (float*)(smraw + 74752);                      // [16][128]
    float* const l_s = (float*)(smraw + 82944);                      // [32][129]

    const int t = threadIdx.x;
    const int r0 = blockIdx.x * 16;

    const int ag = t & 15;
    const int rp = (t >> 4) & 1;
    const int hh = (t >> 5) & 1;
    const int rg = t >> 6;

    const int row = t & 31;    // scan: l_s row (= r_local*2 + h)
    const int sub = t >> 5;    // scan: a-sixteenth 0..7

    const float4* Q4 = (const float4*)g_Q;
    const float4* K4 = (const float4*)g_K;
    const float4* M4 = (const float4*)mask;

    const int sd4 = t & 31;    // staging: d4 lane
    const int sal = t >> 5;    // staging: a base 0..7

    // ---- load Q tile, d4-major (once) ----
#pragma unroll
    for (int p = 0; p < 2; ++p) {
        int e = t + 256 * p;           // 0..511
        int d4 = e & 31, r = e >> 5;   // r 0..15
        q_s[d4 * 17 + r] = Q4[(size_t)(r0 + r) * 32 + d4];
    }

    // per-thread running top-10 over (row, a-sixteenth)
    float bv[10];
    int bi[10];
#pragma unroll
    for (int k = 0; k < 10; ++k) { bv[k] = -1e30f; bi[k] = 0x7fffffff; }

    for (int c = 0; c < N_ATAC / 128; ++c) {
        const int a0 = c * 128;
        __syncthreads();  // prev compute's k_s reads + prev scan's l_s reads done (q_s ready @c=0)

        // ---- stage K chunk [128a][32 d4], coalesced LDG -> STS ----
#pragma unroll
        for (int j = 0; j < 16; ++j) {
            int a = sal + j * 8;
            k_s[sd4 * 129 + a] = K4[(size_t)(a0 + a) * 32 + sd4];
        }
        // ---- stage mask tile [16][128] ----
#pragma unroll
        for (int p = 0; p < 2; ++p) {
            int e = t + 256 * p;
            int rr = e >> 5, c4 = e & 31;
            *(float4*)&m_s[rr * 128 + c4 * 4] =
                M4[(size_t)(r0 + rr) * 2048 + (a0 >> 2) + c4];
        }
        __syncthreads();

        // ---- compute 2r x 8a logits per thread (one head) ----
        float acc[2][8];
#pragma unroll
        for (int i = 0; i < 2; ++i)
#pragma unroll
            for (int j = 0; j < 8; ++j) acc[i][j] = 0.f;

#pragma unroll
        for (int dd = 0; dd < 16; ++dd) {
            const int d4 = hh * 16 + dd;
            float4 kf[8];
#pragma unroll
            for (int j = 0; j < 8; ++j) kf[j] = k_s[d4 * 129 + ag + j * 16];
#pragma unroll
            for (int i = 0; i < 2; ++i) {
                float4 qf = q_s[d4 * 17 + rg * 4 + rp * 2 + i];
#pragma unroll
                for (int j = 0; j < 8; ++j) {
                    acc[i][j] += qf.x * kf[j].x;
                    acc[i][j] += qf.y * kf[j].y;
                    acc[i][j] += qf.z * kf[j].z;
                    acc[i][j] += qf.w * kf[j].w;
                }
            }
        }

        // ---- masked logits -> l_s (sigmoid monotone: rank on logits) ----
#pragma unroll
        for (int i = 0; i < 2; ++i) {
            const int r = rg * 4 + rp * 2 + i;
#pragma unroll
            for (int j = 0; j < 8; ++j) {
                int a = ag + j * 16;
                l_s[(r * 2 + hh) * 129 + a] = acc[i][j] * m_s[r * 128 + a];
            }
        }
        __syncthreads();  // l_s complete; k_s/m_s reads done

        // ---- top-k scan: 16 a's per thread, 4-wide max filter ----
        {
            const float* lp = l_s + row * 129 + sub * 16;
            const int gibase = a0 + sub * 16;
#pragma unroll
            for (int g = 0; g < 4; ++g) {
                float v0 = lp[g * 4 + 0];
                float v1 = lp[g * 4 + 1];
                float v2 = lp[g * 4 + 2];
                float v3 = lp[g * 4 + 3];
                float mx = fmaxf(fmaxf(v0, v1), fmaxf(v2, v3));
                // strict >: ties with the incumbent 10th lose anyway (candidate index
                // is larger than every already-inserted index in this ascending scan)
                if (mx > bv[9]) {
                    int gi = gibase + g * 4;
                    if (tk_better(v0, gi, bv[9], bi[9])) tk_insert(bv, bi, v0, gi);
                    if (tk_better(v1, gi + 1, bv[9], bi[9])) tk_insert(bv, bi, v1, gi + 1);
                    if (tk_better(v2, gi + 2, bv[9], bi[9])) tk_insert(bv, bi, v2, gi + 2);
                    if (tk_better(v3, gi + 3, bv[9], bi[9])) tk_insert(bv, bi, v3, gi + 3);
                }
            }
        }
    }

    __syncthreads();  // all scans done; k_s dead -> overlay

    float* tv = (float*)k_s;            // [32 rows][8 lists][10]  (10240 B)
    int* ti = (int*)(tv + 2560);        // (10240 B)
    float* wv = (float*)(ti + 2560);    // [32*10]
    int* wi = (int*)(wv + 320);         // [32*10]

#pragma unroll
    for (int k = 0; k < 10; ++k) {
        tv[(row * 8 + sub) * 10 + k] = bv[k];
        ti[(row * 8 + sub) * 10 + k] = bi[k];
    }
    __syncthreads();

    // merge 8 partial lists per row -> sigmoid/softmax/threshold weights
    if (t < 32) {
        float fv[10];
        int fi[10];
#pragma unroll
        for (int k = 0; k < 10; ++k) { fv[k] = -1e30f; fi[k] = 0x7fffffff; }
        for (int s = 0; s < 8; ++s)
            for (int k = 0; k < 10; ++k) {
                float v = tv[(t * 8 + s) * 10 + k];
                int gi = ti[(t * 8 + s) * 10 + k];
                if (tk_better(v, gi, fv[9], fi[9])) tk_insert(fv, fi, v, gi);
            }
        float sig[10];
#pragma unroll
        for (int k = 0; k < 10; ++k) sig[k] = 1.f / (1.f + expf(-fv[k]));
        float e[10];
        float den = 0.f;
#pragma unroll
        for (int k = 0; k < 10; ++k) { e[k] = expf(sig[k] - sig[0]); den += e[k]; }
        float inv = 1.f / den;
#pragma unroll
        for (int k = 0; k < 10; ++k) {
            float w = e[k] * inv;
            if (!(sig[k] > THR_S)) w = 0.f;
            wv[t * 10 + k] = w;
            wi[t * 10 + k] = fi[k];
        }
    }
    __syncthreads();

    // sparse aggregation: rna gather (direct) + atac scatter (atomic)
    {
        int d = t & 63, g = t >> 6;   // 4 row-groups x 64 d-lanes
        for (int rr = g; rr < 32; rr += 4) {
            int rloc = rr >> 1, h = rr & 1;
            int r = r0 + rloc;
            float vr = g_VR[(size_t)r * 128 + h * 64 + d];
            float accO = 0.f;
#pragma unroll
            for (int k = 0; k < 10; ++k) {
                float w = wv[rr * 10 + k];
                int a = wi[rr * 10 + k];
                if (w != 0.f) {
                    accO += w * g_VA[(size_t)a * 128 + h * 64 + d];
                    atomicAdd(&g_AGGA[(size_t)a * 128 + h * 64 + d], w * vr);
                }
            }
            g_AGGR[(size_t)r * 128 + h * 64 + d] = accO;
        }
    }
}

// ---------------- launch ----------------
extern "C" void kernel_launch(void* const* d_in, const int* in_sizes, int n_in,
                              void* d_out, int out_size) {
    const float* x_rna = (const float*)d_in[0];
    const float* x_atac = (const float*)d_in[1];
    const float* chrom_mask = (const float*)d_in[2];
    const float* Wq = (const float*)d_in[3];
    const float* bq = (const float*)d_in[4];
    const float* Wk = (const float*)d_in[5];
    const float* bk = (const float*)d_in[6];
    const float* Wvr = (const float*)d_in[7];
    const float* bvr = (const float*)d_in[8];
    const float* Wva = (const float*)d_in[9];
    const float* bva = (const float*)d_in[10];
    const float* Wor = (const float*)d_in[11];
    const float* bor = (const float*)d_in[12];
    const float* Woa = (const float*)d_in[13];
    const float* boa = (const float*)d_in[14];
    const float* Wsr = (const float*)d_in[15];
    const float* bsr = (const float*)d_in[16];
    const float* Wsa = (const float*)d_in[17];
    const float* bsa = (const float*)d_in[18];
    const float* Wdr = (const float*)d_in[19];
    const float* bdr = (const float*)d_in[20];
    const float* Wda = (const float*)d_in[21];
    const float* bda = (const float*)d_in[22];
    float* out = (float*)d_out;

    float *Qp, *Kp, *VRp, *VAp, *AGGRp, *AGGAp, *CRp, *CAp;
    cudaGetSymbolAddress((void**)&Qp, g_Q);
    cudaGetSymbolAddress((void**)&Kp, g_K);
    cudaGetSymbolAddress((void**)&VRp, g_VR);
    cudaGetSymbolAddress((void**)&VAp, g_VA);
    cudaGetSymbolAddress((void**)&AGGRp, g_AGGR);
    cudaGetSymbolAddress((void**)&AGGAp, g_AGGA);
    cudaGetSymbolAddress((void**)&CRp, g_CR);
    cudaGetSymbolAddress((void**)&CAp, g_CA);

    cudaMemsetAsync(AGGAp, 0, (size_t)N_ATAC * HID * sizeof(float));

    GemmBatch b1 = {};
    b1.op[0] = {x_rna, Wq, bq, Qp, N_RNA, IN_C, 128, 0};
    b1.op[1] = {x_atac, Wk, bk, Kp, N_ATAC, IN_C, 128, 0};
    b1.op[2] = {x_rna, Wvr, bvr, VRp, N_RNA, IN_C, 128, 0};
    b1.op[3] = {x_atac, Wva, bva, VAp, N_ATAC, IN_C, 128, 0};
    b1.op[4] = {x_rna, Wsr, bsr, CRp, N_RNA, IN_C, 256, 128};
    b1.op[5] = {x_atac, Wsa, bsa, CAp, N_ATAC, IN_C, 256, 128};
    gemm_kernel<<<dim3(128, 6), 256>>>(b1);

    cudaFuncSetAttribute(attn_kernel, cudaFuncAttributeMaxDynamicSharedMemorySize, 99456);
    attn_kernel<<<N_RNA / 16, 256, 99456>>>(chrom_mask);

    GemmBatch b2 = {};
    b2.op[0] = {AGGRp, Wor, bor, CRp, N_RNA, HID, 256, 0};
    b2.op[1] = {AGGAp, Woa, boa, CAp, N_ATAC, HID, 256, 0};
    gemm_kernel<<<dim3(128, 2), 256>>>(b2);

    GemmBatch b3 = {};
    b3.op[0] = {CRp, Wdr, bdr, out, N_RNA, 2 * HID, 128, 0};
    b3.op[1] = {CAp, Wda, bda, out + (size_t)N_RNA * HID, N_ATAC, 2 * HID, 128, 0};
    gemm_kernel<<<dim3(128, 2), 256>>>(b3);
}

// round 7
// speedup vs baseline: 1.7013x; 1.5434x over previous
#include <cuda_runtime.h>
#include <math.h>
#include <stdint.h>

#define N_RNA 4096
#define N_ATAC 8192
#define IN_C 256
#define HID 128
#define THR_S 0.8f

// ---------------- scratch (static device memory; no allocations) ----------------
__device__ float g_Q[N_RNA * HID];
__device__ float g_K[N_ATAC * HID];
__device__ float g_VR[N_RNA * HID];
__device__ float g_VA[N_ATAC * HID];
__device__ float g_AGGR[N_RNA * HID];
__device__ float g_AGGA[N_ATAC * HID];
__device__ float g_CR[N_RNA * 2 * HID];
__device__ float g_CA[N_ATAC * 2 * HID];

// ---------------- batched GEMM (unchanged, known-good) ----------------
struct GemmOp {
    const float* A;
    const float* W;
    const float* B;
    float* C;
    int M;
    int K;
    int ldc;
    int coff;
};
struct GemmBatch { GemmOp op[6]; };

__global__ void __launch_bounds__(256) gemm_kernel(GemmBatch batch) {
    const GemmOp op = batch.op[blockIdx.y];
    const int m0 = blockIdx.x * 64;
    if (m0 >= op.M) return;

    __shared__ float a_s[64][33];
    __shared__ float w_s[32][128];

    float acc[8][4];
#pragma unroll
    for (int i = 0; i < 8; ++i) {
        acc[i][0] = 0.f; acc[i][1] = 0.f; acc[i][2] = 0.f; acc[i][3] = 0.f;
    }

    const int t = threadIdx.x;
    const float4* A4 = (const float4*)op.A;
    const float4* W4 = (const float4*)op.W;
    const int Kd4 = op.K >> 2;

    for (int kk = 0; kk < op.K; kk += 32) {
        __syncthreads();
        {
            int k4 = t & 7, r = t >> 3;
#pragma unroll
            for (int rr = 0; rr < 2; ++rr) {
                float4 v = A4[(size_t)(m0 + r + rr * 32) * Kd4 + (kk >> 2) + k4];
                a_s[r + rr * 32][k4 * 4 + 0] = v.x;
                a_s[r + rr * 32][k4 * 4 + 1] = v.y;
                a_s[r + rr * 32][k4 * 4 + 2] = v.z;
                a_s[r + rr * 32][k4 * 4 + 3] = v.w;
            }
        }
        {
#pragma unroll
            for (int p = 0; p < 4; ++p) {
                int idx = t + p * 256;
                int k = idx >> 5, c4 = idx & 31;
                *(float4*)&w_s[k][c4 * 4] = W4[(size_t)(kk + k) * 32 + c4];
            }
        }
        __syncthreads();
#pragma unroll
        for (int k = 0; k < 32; ++k) {
            float4 w4 = *(const float4*)&w_s[k][(t & 31) * 4];
#pragma unroll
            for (int i = 0; i < 8; ++i) {
                float av = a_s[(t >> 5) * 8 + i][k];
                acc[i][0] += av * w4.x;
                acc[i][1] += av * w4.y;
                acc[i][2] += av * w4.z;
                acc[i][3] += av * w4.w;
            }
        }
    }

    const int c = (t & 31) * 4;
    const int rb = (t >> 5) * 8;
    float4 b4 = *(const float4*)&op.B[c];
#pragma unroll
    for (int i = 0; i < 8; ++i) {
        size_t row = (size_t)(m0 + rb + i);
        float4 o;
        o.x = acc[i][0] + b4.x;
        o.y = acc[i][1] + b4.y;
        o.z = acc[i][2] + b4.z;
        o.w = acc[i][3] + b4.w;
        *(float4*)&op.C[row * op.ldc + op.coff + c] = o;
    }
}

// ---------------- top-k helpers ----------------
__device__ __forceinline__ bool tk_better(float v, int i, float v2, int i2) {
    // jax top_k order: larger value first, ties -> lower index first
    return (v > v2) || (v == v2 && i < i2);
}

__device__ __forceinline__ void tk_insert(float* bv, int* bi, float v, int gi) {
    bool done = false;
#pragma unroll
    for (int k = 9; k > 0; --k) {
        if (!done) {
            if (tk_better(v, gi, bv[k - 1], bi[k - 1])) {
                bv[k] = bv[k - 1];
                bi[k] = bi[k - 1];
            } else {
                bv[k] = v;
                bi[k] = gi;
                done = true;
            }
        }
    }
    if (!done) { bv[0] = v; bi[0] = gi; }
}

// ---------------- fused attention v6: HEAD-SPLIT blocks ----------------
// Block = 16 rna rows x ONE head; grid = (N_RNA/16) * 2 = 512; 128 threads.
// Identical chunk/barrier/scan structure to the round-2 kernel; per-warp
// FFMA and staging chains halved, kf LDS count per warp unchanged.
//
// Smem (53824 B -> 4 blocks/SM):
//   q_s : float4[16 d4][17]   @ 0      (4352 B)
//   k_s : float4[16 d4][129]  @ 4352   (33024 B)
//   m_s : float [16][128]     @ 37376  (8192 B)
//   l_s : float [16][129]     @ 45568  (8256 B)
// top-k merge buffers overlay k_s after the main loop.

__global__ void __launch_bounds__(128) attn_kernel(const float* __restrict__ mask) {
    extern __shared__ char smraw[];
    float4* const q_s = (float4*)smraw;                 // [16][17]
    float4* const k_s = (float4*)(smraw + 4352);        // [16][129]
    float* const m_s = (float*)(smraw + 37376);         // [16][128]
    float* const l_s = (float*)(smraw + 45568);         // [16][129]

    const int t = threadIdx.x;
    const int r0 = (blockIdx.x >> 1) * 16;
    const int hh = blockIdx.x & 1;       // head of this block

    const int ag = t & 15;               // a-lane (compute)
    const int rp = (t >> 4) & 1;         // row-pair (compute)
    const int rg = t >> 5;               // row-group 0..3 (compute)
    const int row = t & 15;              // scan: l_s row
    const int sub = t >> 4;              // scan: a-sixteenth 0..7

    const float4* Q4 = (const float4*)g_Q;
    const float4* K4 = (const float4*)g_K;
    const float4* M4 = (const float4*)mask;

    const int sd4 = t & 15;              // staging: d4 lane within head
    const int sal = t >> 4;              // staging: a base 0..7

    // ---- load Q tile (this head only), d4-major ----
#pragma unroll
    for (int j = 0; j < 2; ++j) {
        int r = sal + j * 8;             // 0..15
        q_s[sd4 * 17 + r] = Q4[(size_t)(r0 + r) * 32 + hh * 16 + sd4];
    }

    // per-thread running top-10 over (row, a-sixteenth)
    float bv[10];
    int bi[10];
#pragma unroll
    for (int k = 0; k < 10; ++k) { bv[k] = -1e30f; bi[k] = 0x7fffffff; }

    for (int c = 0; c < N_ATAC / 128; ++c) {
        const int a0 = c * 128;
        __syncthreads();  // prev compute k_s reads + prev scan l_s reads done

        // ---- stage K chunk (this head's half): 16 LDG.128 per thread ----
#pragma unroll 8
        for (int j = 0; j < 16; ++j) {
            int a = sal + j * 8;
            k_s[sd4 * 129 + a] = K4[(size_t)(a0 + a) * 32 + hh * 16 + sd4];
        }
        // ---- stage mask tile [16][128] ----
#pragma unroll
        for (int p = 0; p < 4; ++p) {
            int e = t + 128 * p;
            int rr = e >> 5, c4 = e & 31;
            *(float4*)&m_s[rr * 128 + c4 * 4] =
                M4[(size_t)(r0 + rr) * 2048 + (a0 >> 2) + c4];
        }
        __syncthreads();

        // ---- compute 2r x 8a logits per thread ----
        float acc[2][8];
#pragma unroll
        for (int i = 0; i < 2; ++i)
#pragma unroll
            for (int j = 0; j < 8; ++j) acc[i][j] = 0.f;

#pragma unroll
        for (int dd = 0; dd < 16; ++dd) {
            float4 kf[8];
#pragma unroll
            for (int j = 0; j < 8; ++j) kf[j] = k_s[dd * 129 + ag + j * 16];
#pragma unroll
            for (int i = 0; i < 2; ++i) {
                float4 qf = q_s[dd * 17 + rg * 4 + rp * 2 + i];
#pragma unroll
                for (int j = 0; j < 8; ++j) {
                    acc[i][j] += qf.x * kf[j].x;
                    acc[i][j] += qf.y * kf[j].y;
                    acc[i][j] += qf.z * kf[j].z;
                    acc[i][j] += qf.w * kf[j].w;
                }
            }
        }

        // ---- masked logits -> l_s (sigmoid monotone: rank on logits) ----
#pragma unroll
        for (int i = 0; i < 2; ++i) {
            const int r = rg * 4 + rp * 2 + i;
#pragma unroll
            for (int j = 0; j < 8; ++j) {
                int a = ag + j * 16;
                l_s[r * 129 + a] = acc[i][j] * m_s[r * 128 + a];
            }
        }
        __syncthreads();  // l_s complete; k_s/m_s reads done

        // ---- top-k scan: 16 a's per thread (same style as round 2) ----
        {
            const float* lp = l_s + row * 129 + sub * 16;
            const int gibase = a0 + sub * 16;
#pragma unroll 4
            for (int ii = 0; ii < 16; ++ii) {
                float v = lp[ii];
                int gi = gibase + ii;
                if (tk_better(v, gi, bv[9], bi[9])) tk_insert(bv, bi, v, gi);
            }
        }
    }

    __syncthreads();  // all scans done; k_s dead -> overlay

    float* tv = (float*)k_s;            // [16 rows][8 lists][10]  (5120 B)
    int* ti = (int*)(tv + 1280);        // (5120 B)
    float* wv = (float*)(ti + 1280);    // [16*10]
    int* wi = (int*)(wv + 160);         // [16*10]

#pragma unroll
    for (int k = 0; k < 10; ++k) {
        tv[(row * 8 + sub) * 10 + k] = bv[k];
        ti[(row * 8 + sub) * 10 + k] = bi[k];
    }
    __syncthreads();

    // merge 8 partial lists per row -> sigmoid/softmax/threshold weights
    if (t < 16) {
        float fv[10];
        int fi[10];
#pragma unroll
        for (int k = 0; k < 10; ++k) { fv[k] = -1e30f; fi[k] = 0x7fffffff; }
        for (int s = 0; s < 8; ++s)
            for (int k = 0; k < 10; ++k) {
                float v = tv[(t * 8 + s) * 10 + k];
                int gi = ti[(t * 8 + s) * 10 + k];
                if (tk_better(v, gi, fv[9], fi[9])) tk_insert(fv, fi, v, gi);
            }
        float sig[10];
#pragma unroll
        for (int k = 0; k < 10; ++k) sig[k] = 1.f / (1.f + expf(-fv[k]));
        float e[10];
        float den = 0.f;
#pragma unroll
        for (int k = 0; k < 10; ++k) { e[k] = expf(sig[k] - sig[0]); den += e[k]; }
        float inv = 1.f / den;
#pragma unroll
        for (int k = 0; k < 10; ++k) {
            float w = e[k] * inv;
            if (!(sig[k] > THR_S)) w = 0.f;
            wv[t * 10 + k] = w;
            wi[t * 10 + k] = fi[k];
        }
    }
    __syncthreads();

    // sparse aggregation for this head: rna gather + atac scatter (atomic)
    {
        int d = t & 63, g = t >> 6;   // 64 d-lanes (this head's dims), 2 groups
        for (int rr = g; rr < 16; rr += 2) {
            int r = r0 + rr;
            float vr = g_VR[(size_t)r * 128 + hh * 64 + d];
            float accO = 0.f;
#pragma unroll
            for (int k = 0; k < 10; ++k) {
                float w = wv[rr * 10 + k];
                int a = wi[rr * 10 + k];
                if (w != 0.f) {
                    accO += w * g_VA[(size_t)a * 128 + hh * 64 + d];
                    atomicAdd(&g_AGGA[(size_t)a * 128 + hh * 64 + d], w * vr);
                }
            }
            g_AGGR[(size_t)r * 128 + hh * 64 + d] = accO;
        }
    }
}

// ---------------- launch ----------------
extern "C" void kernel_launch(void* const* d_in, const int* in_sizes, int n_in,
                              void* d_out, int out_size) {
    const float* x_rna = (const float*)d_in[0];
    const float* x_atac = (const float*)d_in[1];
    const float* chrom_mask = (const float*)d_in[2];
    const float* Wq = (const float*)d_in[3];
    const float* bq = (const float*)d_in[4];
    const float* Wk = (const float*)d_in[5];
    const float* bk = (const float*)d_in[6];
    const float* Wvr = (const float*)d_in[7];
    const float* bvr = (const float*)d_in[8];
    const float* Wva = (const float*)d_in[9];
    const float* bva = (const float*)d_in[10];
    const float* Wor = (const float*)d_in[11];
    const float* bor = (const float*)d_in[12];
    const float* Woa = (const float*)d_in[13];
    const float* boa = (const float*)d_in[14];
    const float* Wsr = (const float*)d_in[15];
    const float* bsr = (const float*)d_in[16];
    const float* Wsa = (const float*)d_in[17];
    const float* bsa = (const float*)d_in[18];
    const float* Wdr = (const float*)d_in[19];
    const float* bdr = (const float*)d_in[20];
    const float* Wda = (const float*)d_in[21];
    const float* bda = (const float*)d_in[22];
    float* out = (float*)d_out;

    float *Qp, *Kp, *VRp, *VAp, *AGGRp, *AGGAp, *CRp, *CAp;
    cudaGetSymbolAddress((void**)&Qp, g_Q);
    cudaGetSymbolAddress((void**)&Kp, g_K);
    cudaGetSymbolAddress((void**)&VRp, g_VR);
    cudaGetSymbolAddress((void**)&VAp, g_VA);
    cudaGetSymbolAddress((void**)&AGGRp, g_AGGR);
    cudaGetSymbolAddress((void**)&AGGAp, g_AGGA);
    cudaGetSymbolAddress((void**)&CRp, g_CR);
    cudaGetSymbolAddress((void**)&CAp, g_CA);

    cudaMemsetAsync(AGGAp, 0, (size_t)N_ATAC * HID * sizeof(float));

    GemmBatch b1 = {};
    b1.op[0] = {x_rna, Wq, bq, Qp, N_RNA, IN_C, 128, 0};
    b1.op[1] = {x_atac, Wk, bk, Kp, N_ATAC, IN_C, 128, 0};
    b1.op[2] = {x_rna, Wvr, bvr, VRp, N_RNA, IN_C, 128, 0};
    b1.op[3] = {x_atac, Wva, bva, VAp, N_ATAC, IN_C, 128, 0};
    b1.op[4] = {x_rna, Wsr, bsr, CRp, N_RNA, IN_C, 256, 128};
    b1.op[5] = {x_atac, Wsa, bsa, CAp, N_ATAC, IN_C, 256, 128};
    gemm_kernel<<<dim3(128, 6), 256>>>(b1);

    cudaFuncSetAttribute(attn_kernel, cudaFuncAttributeMaxDynamicSharedMemorySize, 53824);
    attn_kernel<<<(N_RNA / 16) * 2, 128, 53824>>>(chrom_mask);

    GemmBatch b2 = {};
    b2.op[0] = {AGGRp, Wor, bor, CRp, N_RNA, HID, 256, 0};
    b2.op[1] = {AGGAp, Woa, boa, CAp, N_ATAC, HID, 256, 0};
    gemm_kernel<<<dim3(128, 2), 256>>>(b2);

    GemmBatch b3 = {};
    b3.op[0] = {CRp, Wdr, bdr, out, N_RNA, 2 * HID, 128, 0};
    b3.op[1] = {CAp, Wda, bda, out + (size_t)N_RNA * HID, N_ATAC, 2 * HID, 128, 0};
    gemm_kernel<<<dim3(128, 2), 256>>>(b3);
}

// round 8
// speedup vs baseline: 1.8174x; 1.0683x over previous
#include <cuda_runtime.h>
#include <math.h>
#include <stdint.h>

#define N_RNA 4096
#define N_ATAC 8192
#define IN_C 256
#define HID 128
#define THR_S 0.8f

// ---------------- scratch (static device memory; no allocations) ----------------
__device__ float g_Q[N_RNA * HID];
__device__ float g_K[N_ATAC * HID];
__device__ float g_VR[N_RNA * HID];
__device__ float g_VA[N_ATAC * HID];
__device__ float g_AGGR[N_RNA * HID];
__device__ float g_AGGA[N_ATAC * HID];
__device__ float g_CR[N_RNA * 2 * HID];
__device__ float g_CA[N_ATAC * 2 * HID];
__device__ float g_L[2u * N_RNA * N_ATAC];   // masked logits [h][r][a]  (268 MB)
__device__ float g_W[2 * N_RNA * 10];        // top-k weights per (h,r)
__device__ int g_WI[2 * N_RNA * 10];         // top-k indices per (h,r)

// ---------------- batched GEMM (unchanged, known-good, 67% FMA) ----------------
struct GemmOp {
    const float* A;
    const float* W;
    const float* B;
    float* C;
    int M;
    int K;
    int ldc;
    int coff;
};
struct GemmBatch { GemmOp op[6]; };

__global__ void __launch_bounds__(256) gemm_kernel(GemmBatch batch) {
    const GemmOp op = batch.op[blockIdx.y];
    const int m0 = blockIdx.x * 64;
    if (m0 >= op.M) return;

    __shared__ float a_s[64][33];
    __shared__ float w_s[32][128];

    float acc[8][4];
#pragma unroll
    for (int i = 0; i < 8; ++i) {
        acc[i][0] = 0.f; acc[i][1] = 0.f; acc[i][2] = 0.f; acc[i][3] = 0.f;
    }

    const int t = threadIdx.x;
    const float4* A4 = (const float4*)op.A;
    const float4* W4 = (const float4*)op.W;
    const int Kd4 = op.K >> 2;

    for (int kk = 0; kk < op.K; kk += 32) {
        __syncthreads();
        {
            int k4 = t & 7, r = t >> 3;
#pragma unroll
            for (int rr = 0; rr < 2; ++rr) {
                float4 v = A4[(size_t)(m0 + r + rr * 32) * Kd4 + (kk >> 2) + k4];
                a_s[r + rr * 32][k4 * 4 + 0] = v.x;
                a_s[r + rr * 32][k4 * 4 + 1] = v.y;
                a_s[r + rr * 32][k4 * 4 + 2] = v.z;
                a_s[r + rr * 32][k4 * 4 + 3] = v.w;
            }
        }
        {
#pragma unroll
            for (int p = 0; p < 4; ++p) {
                int idx = t + p * 256;
                int k = idx >> 5, c4 = idx & 31;
                *(float4*)&w_s[k][c4 * 4] = W4[(size_t)(kk + k) * 32 + c4];
            }
        }
        __syncthreads();
#pragma unroll
        for (int k = 0; k < 32; ++k) {
            float4 w4 = *(const float4*)&w_s[k][(t & 31) * 4];
#pragma unroll
            for (int i = 0; i < 8; ++i) {
                float av = a_s[(t >> 5) * 8 + i][k];
                acc[i][0] += av * w4.x;
                acc[i][1] += av * w4.y;
                acc[i][2] += av * w4.z;
                acc[i][3] += av * w4.w;
            }
        }
    }

    const int c = (t & 31) * 4;
    const int rb = (t >> 5) * 8;
    float4 b4 = *(const float4*)&op.B[c];
#pragma unroll
    for (int i = 0; i < 8; ++i) {
        size_t row = (size_t)(m0 + rb + i);
        float4 o;
        o.x = acc[i][0] + b4.x;
        o.y = acc[i][1] + b4.y;
        o.z = acc[i][2] + b4.z;
        o.w = acc[i][3] + b4.w;
        *(float4*)&op.C[row * op.ldc + op.coff + c] = o;
    }
}

// ---------------- logits GEMM: L[h][r][a] = (Q_h[r] . K_h[a]) * mask[r][a] ----------------
// Tile 128(m) x 128(n) x K=64 (fully resident). 256 threads, 8x8 micro-tiles.
// Smem: a_s[k 64][m 132], b_s[k 64][n 132]  (dynamic, 67584 B)

__global__ void __launch_bounds__(256) logits_kernel(const float* __restrict__ mask) {
    extern __shared__ float sm[];
    float* const a_s = sm;              // [64][132]
    float* const b_s = sm + 64 * 132;   // [64][132]

    const int t = threadIdx.x;
    const int n0 = blockIdx.x * 128;
    const int m0 = blockIdx.y * 128;
    const int h = blockIdx.z;

    const float4* Q4 = (const float4*)g_Q;
    const float4* K4 = (const float4*)g_K;

    // stage Q-tile and K-tile (transposed to [k][m]); one time, conflicts amortized
    {
        const int k4 = t & 15, m = t >> 4;   // m: 0..15
#pragma unroll
        for (int j = 0; j < 8; ++j) {
            int mm = m + j * 16;
            float4 va = Q4[(size_t)(m0 + mm) * 32 + h * 16 + k4];
            a_s[(k4 * 4 + 0) * 132 + mm] = va.x;
            a_s[(k4 * 4 + 1) * 132 + mm] = va.y;
            a_s[(k4 * 4 + 2) * 132 + mm] = va.z;
            a_s[(k4 * 4 + 3) * 132 + mm] = va.w;
            float4 vb = K4[(size_t)(n0 + mm) * 32 + h * 16 + k4];
            b_s[(k4 * 4 + 0) * 132 + mm] = vb.x;
            b_s[(k4 * 4 + 1) * 132 + mm] = vb.y;
            b_s[(k4 * 4 + 2) * 132 + mm] = vb.z;
            b_s[(k4 * 4 + 3) * 132 + mm] = vb.w;
        }
    }
    __syncthreads();

    const int tx = t & 15;     // n micro
    const int ty = t >> 4;     // m micro

    float acc[8][8];
#pragma unroll
    for (int i = 0; i < 8; ++i)
#pragma unroll
        for (int j = 0; j < 8; ++j) acc[i][j] = 0.f;

#pragma unroll 8
    for (int k = 0; k < 64; ++k) {
        float4 a0 = *(const float4*)&a_s[k * 132 + ty * 8];
        float4 a1 = *(const float4*)&a_s[k * 132 + ty * 8 + 4];
        float4 b0 = *(const float4*)&b_s[k * 132 + tx * 8];
        float4 b1 = *(const float4*)&b_s[k * 132 + tx * 8 + 4];
        float ar[8] = {a0.x, a0.y, a0.z, a0.w, a1.x, a1.y, a1.z, a1.w};
        float br[8] = {b0.x, b0.y, b0.z, b0.w, b1.x, b1.y, b1.z, b1.w};
#pragma unroll
        for (int i = 0; i < 8; ++i)
#pragma unroll
            for (int j = 0; j < 8; ++j) acc[i][j] += ar[i] * br[j];
    }

    // epilogue: multiply by mask, store masked logits (sigmoid monotone -> rank later)
    const float4* M4 = (const float4*)mask;
    float4* L4 = (float4*)g_L;
#pragma unroll
    for (int i = 0; i < 8; ++i) {
        const int r = m0 + ty * 8 + i;
        const size_t lrow = ((size_t)h * N_RNA + r) * (N_ATAC / 4);
        const size_t mrow = (size_t)r * (N_ATAC / 4);
#pragma unroll
        for (int jj = 0; jj < 2; ++jj) {
            float4 mv = M4[mrow + (n0 >> 2) + tx * 2 + jj];
            float4 o;
            o.x = acc[i][jj * 4 + 0] * mv.x;
            o.y = acc[i][jj * 4 + 1] * mv.y;
            o.z = acc[i][jj * 4 + 2] * mv.z;
            o.w = acc[i][jj * 4 + 3] * mv.w;
            L4[lrow + (n0 >> 2) + tx * 2 + jj] = o;
        }
    }
}

// ---------------- top-k helpers ----------------
__device__ __forceinline__ bool tk_better(float v, int i, float v2, int i2) {
    // jax top_k order: larger value first, ties -> lower index first
    return (v > v2) || (v == v2 && i < i2);
}

__device__ __forceinline__ void tk_insert(float* bv, int* bi, float v, int gi) {
    bool done = false;
#pragma unroll
    for (int k = 9; k > 0; --k) {
        if (!done) {
            if (tk_better(v, gi, bv[k - 1], bi[k - 1])) {
                bv[k] = bv[k - 1];
                bi[k] = bi[k - 1];
            } else {
                bv[k] = v;
                bi[k] = gi;
                done = true;
            }
        }
    }
    if (!done) { bv[0] = v; bi[0] = gi; }
}

// ---------------- scan kernel: warp per (h,r) row -> exact top-10 -> weights ----------------
// grid: 2*N_RNA/8 blocks of 256 threads (8 warps).
__global__ void __launch_bounds__(256) scan_kernel() {
    __shared__ float tvs[8][32][10];
    __shared__ int tis[8][32][10];

    const int t = threadIdx.x;
    const int w = t >> 5;
    const int lane = t & 31;
    const int ridx = blockIdx.x * 8 + w;          // h*4096 + r

    const float4* L4 = (const float4*)g_L;
    const size_t base = (size_t)ridx * (N_ATAC / 4);

    float bv[10];
    int bi[10];
#pragma unroll
    for (int k = 0; k < 10; ++k) { bv[k] = -1e30f; bi[k] = 0x7fffffff; }

    // lane scans ascending: j outer, float4 of 4 ascending -> tie rule preserved
    for (int j = 0; j < N_ATAC / 128; ++j) {
        float4 v = L4[base + j * 32 + lane];
        int gi = j * 128 + lane * 4;
        float mx = fmaxf(fmaxf(v.x, v.y), fmaxf(v.z, v.w));
        if (mx > bv[9]) {
            if (tk_better(v.x, gi, bv[9], bi[9])) tk_insert(bv, bi, v.x, gi);
            if (tk_better(v.y, gi + 1, bv[9], bi[9])) tk_insert(bv, bi, v.y, gi + 1);
            if (tk_better(v.z, gi + 2, bv[9], bi[9])) tk_insert(bv, bi, v.z, gi + 2);
            if (tk_better(v.w, gi + 3, bv[9], bi[9])) tk_insert(bv, bi, v.w, gi + 3);
        }
    }

#pragma unroll
    for (int k = 0; k < 10; ++k) { tvs[w][lane][k] = bv[k]; tis[w][lane][k] = bi[k]; }
    __syncwarp();

    // stage 1: lanes 0..7 each merge 4 lists
    if (lane < 8) {
        float fv[10];
        int fi[10];
#pragma unroll
        for (int k = 0; k < 10; ++k) { fv[k] = -1e30f; fi[k] = 0x7fffffff; }
        for (int s = 0; s < 4; ++s)
            for (int k = 0; k < 10; ++k) {
                float v = tvs[w][lane * 4 + s][k];
                int gi = tis[w][lane * 4 + s][k];
                if (tk_better(v, gi, fv[9], fi[9])) tk_insert(fv, fi, v, gi);
            }
#pragma unroll
        for (int k = 0; k < 10; ++k) { tvs[w][lane][k] = fv[k]; tis[w][lane][k] = fi[k]; }
    }
    __syncwarp();

    // stage 2: lane 0 merges 8 lists, computes weights
    if (lane == 0) {
        float fv[10];
        int fi[10];
#pragma unroll
        for (int k = 0; k < 10; ++k) { fv[k] = -1e30f; fi[k] = 0x7fffffff; }
        for (int s = 0; s < 8; ++s)
            for (int k = 0; k < 10; ++k) {
                float v = tvs[w][s][k];
                int gi = tis[w][s][k];
                if (tk_better(v, gi, fv[9], fi[9])) tk_insert(fv, fi, v, gi);
            }
        float sig[10];
#pragma unroll
        for (int k = 0; k < 10; ++k) sig[k] = 1.f / (1.f + expf(-fv[k]));
        float e[10];
        float den = 0.f;
#pragma unroll
        for (int k = 0; k < 10; ++k) { e[k] = expf(sig[k] - sig[0]); den += e[k]; }
        float inv = 1.f / den;
#pragma unroll
        for (int k = 0; k < 10; ++k) {
            float ww = e[k] * inv;
            if (!(sig[k] > THR_S)) ww = 0.f;
            g_W[ridx * 10 + k] = ww;
            g_WI[ridx * 10 + k] = fi[k];
        }
    }
}

// ---------------- aggregation kernel: sparse gather + scatter ----------------
// block 256 = 4 x (64 d-lanes); each 64-lane group handles one (h,r).
__global__ void __launch_bounds__(256) agg_kernel() {
    const int t = threadIdx.x;
    const int d = t & 63;
    const int q = t >> 6;
    const int ridx = blockIdx.x * 4 + q;
    const int h = ridx >> 12;
    const int r = ridx & 4095;

    float wv[10];
    int wi[10];
#pragma unroll
    for (int k = 0; k < 10; ++k) { wv[k] = g_W[ridx * 10 + k]; wi[k] = g_WI[ridx * 10 + k]; }

    const float vr = g_VR[(size_t)r * 128 + h * 64 + d];
    float accO = 0.f;
#pragma unroll
    for (int k = 0; k < 10; ++k) {
        float w = wv[k];
        int a = wi[k];
        if (w != 0.f) {
            accO += w * g_VA[(size_t)a * 128 + h * 64 + d];
            atomicAdd(&g_AGGA[(size_t)a * 128 + h * 64 + d], w * vr);
        }
    }
    g_AGGR[(size_t)r * 128 + h * 64 + d] = accO;
}

// ---------------- launch ----------------
extern "C" void kernel_launch(void* const* d_in, const int* in_sizes, int n_in,
                              void* d_out, int out_size) {
    const float* x_rna = (const float*)d_in[0];
    const float* x_atac = (const float*)d_in[1];
    const float* chrom_mask = (const float*)d_in[2];
    const float* Wq = (const float*)d_in[3];
    const float* bq = (const float*)d_in[4];
    const float* Wk = (const float*)d_in[5];
    const float* bk = (const float*)d_in[6];
    const float* Wvr = (const float*)d_in[7];
    const float* bvr = (const float*)d_in[8];
    const float* Wva = (const float*)d_in[9];
    const float* bva = (const float*)d_in[10];
    const float* Wor = (const float*)d_in[11];
    const float* bor = (const float*)d_in[12];
    const float* Woa = (const float*)d_in[13];
    const float* boa = (const float*)d_in[14];
    const float* Wsr = (const float*)d_in[15];
    const float* bsr = (const float*)d_in[16];
    const float* Wsa = (const float*)d_in[17];
    const float* bsa = (const float*)d_in[18];
    const float* Wdr = (const float*)d_in[19];
    const float* bdr = (const float*)d_in[20];
    const float* Wda = (const float*)d_in[21];
    const float* bda = (const float*)d_in[22];
    float* out = (float*)d_out;

    float *Qp, *Kp, *VRp, *VAp, *AGGRp, *AGGAp, *CRp, *CAp;
    cudaGetSymbolAddress((void**)&Qp, g_Q);
    cudaGetSymbolAddress((void**)&Kp, g_K);
    cudaGetSymbolAddress((void**)&VRp, g_VR);
    cudaGetSymbolAddress((void**)&VAp, g_VA);
    cudaGetSymbolAddress((void**)&AGGRp, g_AGGR);
    cudaGetSymbolAddress((void**)&AGGAp, g_AGGA);
    cudaGetSymbolAddress((void**)&CRp, g_CR);
    cudaGetSymbolAddress((void**)&CAp, g_CA);

    cudaMemsetAsync(AGGAp, 0, (size_t)N_ATAC * HID * sizeof(float));

    // input projections
    GemmBatch b1 = {};
    b1.op[0] = {x_rna, Wq, bq, Qp, N_RNA, IN_C, 128, 0};
    b1.op[1] = {x_atac, Wk, bk, Kp, N_ATAC, IN_C, 128, 0};
    b1.op[2] = {x_rna, Wvr, bvr, VRp, N_RNA, IN_C, 128, 0};
    b1.op[3] = {x_atac, Wva, bva, VAp, N_ATAC, IN_C, 128, 0};
    b1.op[4] = {x_rna, Wsr, bsr, CRp, N_RNA, IN_C, 256, 128};
    b1.op[5] = {x_atac, Wsa, bsa, CAp, N_ATAC, IN_C, 256, 128};
    gemm_kernel<<<dim3(128, 6), 256>>>(b1);

    // masked logits GEMM
    cudaFuncSetAttribute(logits_kernel, cudaFuncAttributeMaxDynamicSharedMemorySize, 67584);
    logits_kernel<<<dim3(N_ATAC / 128, N_RNA / 128, 2), 256, 67584>>>(chrom_mask);

    // exact top-10 + weights
    scan_kernel<<<2 * N_RNA / 8, 256>>>();

    // sparse aggregation
    agg_kernel<<<2 * N_RNA / 4, 256>>>();

    // out-projections into concat halves
    GemmBatch b2 = {};
    b2.op[0] = {AGGRp, Wor, bor, CRp, N_RNA, HID, 256, 0};
    b2.op[1] = {AGGAp, Woa, boa, CAp, N_ATAC, HID, 256, 0};
    gemm_kernel<<<dim3(128, 2), 256>>>(b2);

    // dim-reduction GEMMs into d_out
    GemmBatch b3 = {};
    b3.op[0] = {CRp, Wdr, bdr, out, N_RNA, 2 * HID, 128, 0};
    b3.op[1] = {CAp, Wda, bda, out + (size_t)N_RNA * HID, N_ATAC, 2 * HID, 128, 0};
    gemm_kernel<<<dim3(128, 2), 256>>>(b3);
}

// round 9
// speedup vs baseline: 1.9192x; 1.0560x over previous
#include <cuda_runtime.h>
#include <math.h>
#include <stdint.h>

#define N_RNA 4096
#define N_ATAC 8192
#define IN_C 256
#define HID 128
#define THR_S 0.8f

// ---------------- scratch (static device memory; no allocations) ----------------
__device__ float g_Q[N_RNA * HID];
__device__ float g_K[N_ATAC * HID];
__device__ float g_KT[HID * N_ATAC];         // K transposed: [d 128][a 8192]
__device__ float g_VR[N_RNA * HID];
__device__ float g_VA[N_ATAC * HID];
__device__ float g_AGGR[N_RNA * HID];
__device__ float g_AGGA[N_ATAC * HID];
__device__ float g_CR[N_RNA * 2 * HID];
__device__ float g_CA[N_ATAC * 2 * HID];
__device__ float g_L[2u * N_RNA * N_ATAC];   // masked logits [h][r][a]  (268 MB)
__device__ float g_W[2 * N_RNA * 10];        // top-k weights per (h,r)
__device__ int g_WI[2 * N_RNA * 10];         // top-k indices per (h,r)

// ---------------- batched GEMM (unchanged, known-good, 67% FMA) ----------------
struct GemmOp {
    const float* A;
    const float* W;
    const float* B;
    float* C;
    int M;
    int K;
    int ldc;
    int coff;
};
struct GemmBatch { GemmOp op[6]; };

__global__ void __launch_bounds__(256) gemm_kernel(GemmBatch batch) {
    const GemmOp op = batch.op[blockIdx.y];
    const int m0 = blockIdx.x * 64;
    if (m0 >= op.M) return;

    __shared__ float a_s[64][33];
    __shared__ float w_s[32][128];

    float acc[8][4];
#pragma unroll
    for (int i = 0; i < 8; ++i) {
        acc[i][0] = 0.f; acc[i][1] = 0.f; acc[i][2] = 0.f; acc[i][3] = 0.f;
    }

    const int t = threadIdx.x;
    const float4* A4 = (const float4*)op.A;
    const float4* W4 = (const float4*)op.W;
    const int Kd4 = op.K >> 2;

    for (int kk = 0; kk < op.K; kk += 32) {
        __syncthreads();
        {
            int k4 = t & 7, r = t >> 3;
#pragma unroll
            for (int rr = 0; rr < 2; ++rr) {
                float4 v = A4[(size_t)(m0 + r + rr * 32) * Kd4 + (kk >> 2) + k4];
                a_s[r + rr * 32][k4 * 4 + 0] = v.x;
                a_s[r + rr * 32][k4 * 4 + 1] = v.y;
                a_s[r + rr * 32][k4 * 4 + 2] = v.z;
                a_s[r + rr * 32][k4 * 4 + 3] = v.w;
            }
        }
        {
#pragma unroll
            for (int p = 0; p < 4; ++p) {
                int idx = t + p * 256;
                int k = idx >> 5, c4 = idx & 31;
                *(float4*)&w_s[k][c4 * 4] = W4[(size_t)(kk + k) * 32 + c4];
            }
        }
        __syncthreads();
#pragma unroll
        for (int k = 0; k < 32; ++k) {
            float4 w4 = *(const float4*)&w_s[k][(t & 31) * 4];
#pragma unroll
            for (int i = 0; i < 8; ++i) {
                float av = a_s[(t >> 5) * 8 + i][k];
                acc[i][0] += av * w4.x;
                acc[i][1] += av * w4.y;
                acc[i][2] += av * w4.z;
                acc[i][3] += av * w4.w;
            }
        }
    }

    const int c = (t & 31) * 4;
    const int rb = (t >> 5) * 8;
    float4 b4 = *(const float4*)&op.B[c];
#pragma unroll
    for (int i = 0; i < 8; ++i) {
        size_t row = (size_t)(m0 + rb + i);
        float4 o;
        o.x = acc[i][0] + b4.x;
        o.y = acc[i][1] + b4.y;
        o.z = acc[i][2] + b4.z;
        o.w = acc[i][3] + b4.w;
        *(float4*)&op.C[row * op.ldc + op.coff + c] = o;
    }
}

// ---------------- K transpose: g_K[a][d] -> g_KT[d][a] ----------------
// 64 a-rows per block; smem tile with odd padding (scalar stores OK, float4 reads after)
__global__ void __launch_bounds__(256) transpose_k() {
    __shared__ float ts[64][133];
    const int t = threadIdx.x;
    const int a0 = blockIdx.x * 64;
    const float4* K4 = (const float4*)g_K;
#pragma unroll
    for (int j = 0; j < 8; ++j) {
        int idx = t + 256 * j;            // 0..2047
        int r = idx >> 5, c4 = idx & 31;
        float4 v = K4[(size_t)(a0 + r) * 32 + c4];
        ts[r][c4 * 4 + 0] = v.x;
        ts[r][c4 * 4 + 1] = v.y;
        ts[r][c4 * 4 + 2] = v.z;
        ts[r][c4 * 4 + 3] = v.w;
    }
    __syncthreads();
    float4* KT4 = (float4*)g_KT;
#pragma unroll
    for (int j = 0; j < 8; ++j) {
        int idx = t + 256 * j;            // 0..2047
        int d = idx >> 4, ac4 = idx & 15;
        float4 o;
        o.x = ts[ac4 * 4 + 0][d];
        o.y = ts[ac4 * 4 + 1][d];
        o.z = ts[ac4 * 4 + 2][d];
        o.w = ts[ac4 * 4 + 3][d];
        KT4[((size_t)d * N_ATAC + a0) / 4 + ac4] = o;
    }
}

// ---------------- logits GEMM v2: conflict-free smem access ----------------
// L[h][r][a] = (Q_h[r] . K_h[a]) * mask[r][a]
// Tile 128m x 128n x K=64 resident. 256 threads: tx = t&31 (n), ty = t>>5 (m).
// Micro-tile 16m x 4n. A: row-major broadcast scalar LDS; B: k-major lane-consecutive LDS.128.
// Smem: a_s[128 m][68 f]  34816 B ; b_s[64 k][33 f4] 33792 B ; total 68608 B.

__global__ void __launch_bounds__(256, 2) logits_kernel(const float* __restrict__ mask) {
    extern __shared__ float sm[];
    float* const a_f = sm;                       // [128][68] floats
    float4* const b4_s = (float4*)(sm + 128 * 68);  // [64][33] float4

    const int t = threadIdx.x;
    const int n0 = blockIdx.x * 128;
    const int m0 = blockIdx.y * 128;
    const int h = blockIdx.z;

    // ---- stage A tile [128 m][64 k] (no transpose; direct from g_Q) ----
    {
        const float4* Q4 = (const float4*)g_Q;
        float4* a4 = (float4*)a_f;               // row stride 17 float4
        const int k4 = t & 15, mq = t >> 4;      // mq 0..15
#pragma unroll
        for (int j = 0; j < 8; ++j) {
            int mm = mq + 16 * j;
            a4[mm * 17 + k4] = Q4[(size_t)(m0 + mm) * 32 + h * 16 + k4];
        }
    }
    // ---- stage B tile [64 k][128 n] (direct from g_KT; coalesced both sides) ----
    {
        const float4* KT4 = (const float4*)g_KT;
        const int gq = t & 31, k2 = t >> 5;      // k2 0..7
#pragma unroll
        for (int j = 0; j < 8; ++j) {
            int k = k2 + 8 * j;
            b4_s[k * 33 + gq] =
                KT4[((size_t)(h * 64 + k) * N_ATAC + n0) / 4 + gq];
        }
    }
    __syncthreads();

    const int tx = t & 31;
    const int ty = t >> 5;

    float acc[16][4];
#pragma unroll
    for (int i = 0; i < 16; ++i) {
        acc[i][0] = 0.f; acc[i][1] = 0.f; acc[i][2] = 0.f; acc[i][3] = 0.f;
    }

    const float* arow = a_f + ty * 16 * 68;      // this warp's 16 m-rows

#pragma unroll 4
    for (int k = 0; k < 64; ++k) {
        float4 b = b4_s[k * 33 + tx];
#pragma unroll
        for (int i = 0; i < 16; ++i) {
            float av = arow[i * 68 + k];          // warp-uniform broadcast
            acc[i][0] += av * b.x;
            acc[i][1] += av * b.y;
            acc[i][2] += av * b.z;
            acc[i][3] += av * b.w;
        }
    }

    // ---- epilogue: mask multiply + store ----
    const float4* M4 = (const float4*)mask;
    float4* L4 = (float4*)g_L;
#pragma unroll
    for (int i = 0; i < 16; ++i) {
        const int r = m0 + ty * 16 + i;
        float4 mv = M4[(size_t)r * (N_ATAC / 4) + (n0 >> 2) + tx];
        float4 o;
        o.x = acc[i][0] * mv.x;
        o.y = acc[i][1] * mv.y;
        o.z = acc[i][2] * mv.z;
        o.w = acc[i][3] * mv.w;
        L4[((size_t)h * N_RNA + r) * (N_ATAC / 4) + (n0 >> 2) + tx] = o;
    }
}

// ---------------- top-k helpers ----------------
__device__ __forceinline__ bool tk_better(float v, int i, float v2, int i2) {
    // jax top_k order: larger value first, ties -> lower index first
    return (v > v2) || (v == v2 && i < i2);
}

__device__ __forceinline__ void tk_insert(float* bv, int* bi, float v, int gi) {
    bool done = false;
#pragma unroll
    for (int k = 9; k > 0; --k) {
        if (!done) {
            if (tk_better(v, gi, bv[k - 1], bi[k - 1])) {
                bv[k] = bv[k - 1];
                bi[k] = bi[k - 1];
            } else {
                bv[k] = v;
                bi[k] = gi;
                done = true;
            }
        }
    }
    if (!done) { bv[0] = v; bi[0] = gi; }
}

// ---------------- scan kernel: warp per (h,r) row -> exact top-10 -> weights ----------------
__global__ void __launch_bounds__(256) scan_kernel() {
    __shared__ float tvs[8][32][10];
    __shared__ int tis[8][32][10];

    const int t = threadIdx.x;
    const int w = t >> 5;
    const int lane = t & 31;
    const int ridx = blockIdx.x * 8 + w;          // h*4096 + r

    const float4* L4 = (const float4*)g_L;
    const size_t base = (size_t)ridx * (N_ATAC / 4);

    float bv[10];
    int bi[10];
#pragma unroll
    for (int k = 0; k < 10; ++k) { bv[k] = -1e30f; bi[k] = 0x7fffffff; }

    for (int j = 0; j < N_ATAC / 128; ++j) {
        float4 v = L4[base + j * 32 + lane];
        int gi = j * 128 + lane * 4;
        float mx = fmaxf(fmaxf(v.x, v.y), fmaxf(v.z, v.w));
        if (mx > bv[9]) {
            if (tk_better(v.x, gi, bv[9], bi[9])) tk_insert(bv, bi, v.x, gi);
            if (tk_better(v.y, gi + 1, bv[9], bi[9])) tk_insert(bv, bi, v.y, gi + 1);
            if (tk_better(v.z, gi + 2, bv[9], bi[9])) tk_insert(bv, bi, v.z, gi + 2);
            if (tk_better(v.w, gi + 3, bv[9], bi[9])) tk_insert(bv, bi, v.w, gi + 3);
        }
    }

#pragma unroll
    for (int k = 0; k < 10; ++k) { tvs[w][lane][k] = bv[k]; tis[w][lane][k] = bi[k]; }
    __syncwarp();

    if (lane < 8) {
        float fv[10];
        int fi[10];
#pragma unroll
        for (int k = 0; k < 10; ++k) { fv[k] = -1e30f; fi[k] = 0x7fffffff; }
        for (int s = 0; s < 4; ++s)
            for (int k = 0; k < 10; ++k) {
                float v = tvs[w][lane * 4 + s][k];
                int gi = tis[w][lane * 4 + s][k];
                if (tk_better(v, gi, fv[9], fi[9])) tk_insert(fv, fi, v, gi);
            }
#pragma unroll
        for (int k = 0; k < 10; ++k) { tvs[w][lane][k] = fv[k]; tis[w][lane][k] = fi[k]; }
    }
    __syncwarp();

    if (lane == 0) {
        float fv[10];
        int fi[10];
#pragma unroll
        for (int k = 0; k < 10; ++k) { fv[k] = -1e30f; fi[k] = 0x7fffffff; }
        for (int s = 0; s < 8; ++s)
            for (int k = 0; k < 10; ++k) {
                float v = tvs[w][s][k];
                int gi = tis[w][s][k];
                if (tk_better(v, gi, fv[9], fi[9])) tk_insert(fv, fi, v, gi);
            }
        float sig[10];
#pragma unroll
        for (int k = 0; k < 10; ++k) sig[k] = 1.f / (1.f + expf(-fv[k]));
        float e[10];
        float den = 0.f;
#pragma unroll
        for (int k = 0; k < 10; ++k) { e[k] = expf(sig[k] - sig[0]); den += e[k]; }
        float inv = 1.f / den;
#pragma unroll
        for (int k = 0; k < 10; ++k) {
            float ww = e[k] * inv;
            if (!(sig[k] > THR_S)) ww = 0.f;
            g_W[ridx * 10 + k] = ww;
            g_WI[ridx * 10 + k] = fi[k];
        }
    }
}

// ---------------- aggregation kernel: sparse gather + scatter ----------------
__global__ void __launch_bounds__(256) agg_kernel() {
    const int t = threadIdx.x;
    const int d = t & 63;
    const int q = t >> 6;
    const int ridx = blockIdx.x * 4 + q;
    const int h = ridx >> 12;
    const int r = ridx & 4095;

    float wv[10];
    int wi[10];
#pragma unroll
    for (int k = 0; k < 10; ++k) { wv[k] = g_W[ridx * 10 + k]; wi[k] = g_WI[ridx * 10 + k]; }

    const float vr = g_VR[(size_t)r * 128 + h * 64 + d];
    float accO = 0.f;
#pragma unroll
    for (int k = 0; k < 10; ++k) {
        float w = wv[k];
        int a = wi[k];
        if (w != 0.f) {
            accO += w * g_VA[(size_t)a * 128 + h * 64 + d];
            atomicAdd(&g_AGGA[(size_t)a * 128 + h * 64 + d], w * vr);
        }
    }
    g_AGGR[(size_t)r * 128 + h * 64 + d] = accO;
}

// ---------------- launch ----------------
extern "C" void kernel_launch(void* const* d_in, const int* in_sizes, int n_in,
                              void* d_out, int out_size) {
    const float* x_rna = (const float*)d_in[0];
    const float* x_atac = (const float*)d_in[1];
    const float* chrom_mask = (const float*)d_in[2];
    const float* Wq = (const float*)d_in[3];
    const float* bq = (const float*)d_in[4];
    const float* Wk = (const float*)d_in[5];
    const float* bk = (const float*)d_in[6];
    const float* Wvr = (const float*)d_in[7];
    const float* bvr = (const float*)d_in[8];
    const float* Wva = (const float*)d_in[9];
    const float* bva = (const float*)d_in[10];
    const float* Wor = (const float*)d_in[11];
    const float* bor = (const float*)d_in[12];
    const float* Woa = (const float*)d_in[13];
    const float* boa = (const float*)d_in[14];
    const float* Wsr = (const float*)d_in[15];
    const float* bsr = (const float*)d_in[16];
    const float* Wsa = (const float*)d_in[17];
    const float* bsa = (const float*)d_in[18];
    const float* Wdr = (const float*)d_in[19];
    const float* bdr = (const float*)d_in[20];
    const float* Wda = (const float*)d_in[21];
    const float* bda = (const float*)d_in[22];
    float* out = (float*)d_out;

    float *Qp, *Kp, *VRp, *VAp, *AGGRp, *AGGAp, *CRp, *CAp;
    cudaGetSymbolAddress((void**)&Qp, g_Q);
    cudaGetSymbolAddress((void**)&Kp, g_K);
    cudaGetSymbolAddress((void**)&VRp, g_VR);
    cudaGetSymbolAddress((void**)&VAp, g_VA);
    cudaGetSymbolAddress((void**)&AGGRp, g_AGGR);
    cudaGetSymbolAddress((void**)&AGGAp, g_AGGA);
    cudaGetSymbolAddress((void**)&CRp, g_CR);
    cudaGetSymbolAddress((void**)&CAp, g_CA);

    cudaMemsetAsync(AGGAp, 0, (size_t)N_ATAC * HID * sizeof(float));

    // input projections
    GemmBatch b1 = {};
    b1.op[0] = {x_rna, Wq, bq, Qp, N_RNA, IN_C, 128, 0};
    b1.op[1] = {x_atac, Wk, bk, Kp, N_ATAC, IN_C, 128, 0};
    b1.op[2] = {x_rna, Wvr, bvr, VRp, N_RNA, IN_C, 128, 0};
    b1.op[3] = {x_atac, Wva, bva, VAp, N_ATAC, IN_C, 128, 0};
    b1.op[4] = {x_rna, Wsr, bsr, CRp, N_RNA, IN_C, 256, 128};
    b1.op[5] = {x_atac, Wsa, bsa, CAp, N_ATAC, IN_C, 256, 128};
    gemm_kernel<<<dim3(128, 6), 256>>>(b1);

    // K -> KT
    transpose_k<<<N_ATAC / 64, 256>>>();

    // masked logits GEMM (conflict-free)
    cudaFuncSetAttribute(logits_kernel, cudaFuncAttributeMaxDynamicSharedMemorySize, 68608);
    logits_kernel<<<dim3(N_ATAC / 128, N_RNA / 128, 2), 256, 68608>>>(chrom_mask);

    // exact top-10 + weights
    scan_kernel<<<2 * N_RNA / 8, 256>>>();

    // sparse aggregation
    agg_kernel<<<2 * N_RNA / 4, 256>>>();

    // out-projections into concat halves
    GemmBatch b2 = {};
    b2.op[0] = {AGGRp, Wor, bor, CRp, N_RNA, HID, 256, 0};
    b2.op[1] = {AGGAp, Woa, boa, CAp, N_ATAC, HID, 256, 0};
    gemm_kernel<<<dim3(128, 2), 256>>>(b2);

    // dim-reduction GEMMs into d_out
    GemmBatch b3 = {};
    b3.op[0] = {CRp, Wdr, bdr, out, N_RNA, 2 * HID, 128, 0};
    b3.op[1] = {CAp, Wda, bda, out + (size_t)N_RNA * HID, N_ATAC, 2 * HID, 128, 0};
    gemm_kernel<<<dim3(128, 2), 256>>>(b3);
}

// round 10
// speedup vs baseline: 2.3390x; 1.2187x over previous
#include <cuda_runtime.h>
#include <math.h>
#include <stdint.h>

#define N_RNA 4096
#define N_ATAC 8192
#define IN_C 256
#define HID 128
#define THR_S 0.8f

// ---------------- scratch (static device memory; no allocations) ----------------
__device__ float g_Q[N_RNA * HID];
__device__ float g_K[N_ATAC * HID];
__device__ float g_KT[HID * N_ATAC];          // K transposed: [d 128][a 8192]
__device__ float g_VR[N_RNA * HID];
__device__ float g_VA[N_ATAC * HID];
__device__ float g_AGGR[N_RNA * HID];
__device__ float g_AGGA[N_ATAC * HID];
__device__ float g_CR[N_RNA * 2 * HID];
__device__ float g_CA[N_ATAC * 2 * HID];
__device__ float g_L[2u * N_RNA * N_ATAC];    // masked logits [h][r][a]  (268 MB)
__device__ float g_LM[2u * N_RNA * (N_ATAC / 4)];  // group-of-4 maxes (67 MB)
__device__ float g_W[2 * N_RNA * 10];         // top-k weights per (h,r)
__device__ int g_WI[2 * N_RNA * 10];          // top-k indices per (h,r)

// ---------------- batched GEMM (unchanged, known-good) ----------------
struct GemmOp {
    const float* A;
    const float* W;
    const float* B;
    float* C;
    int M;
    int K;
    int ldc;
    int coff;
};
struct GemmBatch { GemmOp op[6]; };

__global__ void __launch_bounds__(256) gemm_kernel(GemmBatch batch) {
    const GemmOp op = batch.op[blockIdx.y];
    const int m0 = blockIdx.x * 64;
    if (m0 >= op.M) return;

    __shared__ float a_s[64][33];
    __shared__ float w_s[32][128];

    float acc[8][4];
#pragma unroll
    for (int i = 0; i < 8; ++i) {
        acc[i][0] = 0.f; acc[i][1] = 0.f; acc[i][2] = 0.f; acc[i][3] = 0.f;
    }

    const int t = threadIdx.x;
    const float4* A4 = (const float4*)op.A;
    const float4* W4 = (const float4*)op.W;
    const int Kd4 = op.K >> 2;

    for (int kk = 0; kk < op.K; kk += 32) {
        __syncthreads();
        {
            int k4 = t & 7, r = t >> 3;
#pragma unroll
            for (int rr = 0; rr < 2; ++rr) {
                float4 v = A4[(size_t)(m0 + r + rr * 32) * Kd4 + (kk >> 2) + k4];
                a_s[r + rr * 32][k4 * 4 + 0] = v.x;
                a_s[r + rr * 32][k4 * 4 + 1] = v.y;
                a_s[r + rr * 32][k4 * 4 + 2] = v.z;
                a_s[r + rr * 32][k4 * 4 + 3] = v.w;
            }
        }
        {
#pragma unroll
            for (int p = 0; p < 4; ++p) {
                int idx = t + p * 256;
                int k = idx >> 5, c4 = idx & 31;
                *(float4*)&w_s[k][c4 * 4] = W4[(size_t)(kk + k) * 32 + c4];
            }
        }
        __syncthreads();
#pragma unroll
        for (int k = 0; k < 32; ++k) {
            float4 w4 = *(const float4*)&w_s[k][(t & 31) * 4];
#pragma unroll
            for (int i = 0; i < 8; ++i) {
                float av = a_s[(t >> 5) * 8 + i][k];
                acc[i][0] += av * w4.x;
                acc[i][1] += av * w4.y;
                acc[i][2] += av * w4.z;
                acc[i][3] += av * w4.w;
            }
        }
    }

    const int c = (t & 31) * 4;
    const int rb = (t >> 5) * 8;
    float4 b4 = *(const float4*)&op.B[c];
#pragma unroll
    for (int i = 0; i < 8; ++i) {
        size_t row = (size_t)(m0 + rb + i);
        float4 o;
        o.x = acc[i][0] + b4.x;
        o.y = acc[i][1] + b4.y;
        o.z = acc[i][2] + b4.z;
        o.w = acc[i][3] + b4.w;
        *(float4*)&op.C[row * op.ldc + op.coff + c] = o;
    }
}

// ---------------- K transpose: g_K[a][d] -> g_KT[d][a] ----------------
__global__ void __launch_bounds__(256) transpose_k() {
    __shared__ float ts[64][133];
    const int t = threadIdx.x;
    const int a0 = blockIdx.x * 64;
    const float4* K4 = (const float4*)g_K;
#pragma unroll
    for (int j = 0; j < 8; ++j) {
        int idx = t + 256 * j;
        int r = idx >> 5, c4 = idx & 31;
        float4 v = K4[(size_t)(a0 + r) * 32 + c4];
        ts[r][c4 * 4 + 0] = v.x;
        ts[r][c4 * 4 + 1] = v.y;
        ts[r][c4 * 4 + 2] = v.z;
        ts[r][c4 * 4 + 3] = v.w;
    }
    __syncthreads();
    float4* KT4 = (float4*)g_KT;
#pragma unroll
    for (int j = 0; j < 8; ++j) {
        int idx = t + 256 * j;
        int d = idx >> 4, ac4 = idx & 15;
        float4 o;
        o.x = ts[ac4 * 4 + 0][d];
        o.y = ts[ac4 * 4 + 1][d];
        o.z = ts[ac4 * 4 + 2][d];
        o.w = ts[ac4 * 4 + 3][d];
        KT4[((size_t)d * N_ATAC + a0) / 4 + ac4] = o;
    }
}

// ---------------- logits GEMM (conflict-free) + group-max emission ----------------
__global__ void __launch_bounds__(256, 2) logits_kernel(const float* __restrict__ mask) {
    extern __shared__ float sm[];
    float* const a_f = sm;                          // [128][68] floats
    float4* const b4_s = (float4*)(sm + 128 * 68);  // [64][33] float4

    const int t = threadIdx.x;
    const int n0 = blockIdx.x * 128;
    const int m0 = blockIdx.y * 128;
    const int h = blockIdx.z;

    {
        const float4* Q4 = (const float4*)g_Q;
        float4* a4 = (float4*)a_f;
        const int k4 = t & 15, mq = t >> 4;
#pragma unroll
        for (int j = 0; j < 8; ++j) {
            int mm = mq + 16 * j;
            a4[mm * 17 + k4] = Q4[(size_t)(m0 + mm) * 32 + h * 16 + k4];
        }
    }
    {
        const float4* KT4 = (const float4*)g_KT;
        const int gq = t & 31, k2 = t >> 5;
#pragma unroll
        for (int j = 0; j < 8; ++j) {
            int k = k2 + 8 * j;
            b4_s[k * 33 + gq] =
                KT4[((size_t)(h * 64 + k) * N_ATAC + n0) / 4 + gq];
        }
    }
    __syncthreads();

    const int tx = t & 31;
    const int ty = t >> 5;

    float acc[16][4];
#pragma unroll
    for (int i = 0; i < 16; ++i) {
        acc[i][0] = 0.f; acc[i][1] = 0.f; acc[i][2] = 0.f; acc[i][3] = 0.f;
    }

    const float* arow = a_f + ty * 16 * 68;

#pragma unroll 4
    for (int k = 0; k < 64; ++k) {
        float4 b = b4_s[k * 33 + tx];
#pragma unroll
        for (int i = 0; i < 16; ++i) {
            float av = arow[i * 68 + k];
            acc[i][0] += av * b.x;
            acc[i][1] += av * b.y;
            acc[i][2] += av * b.z;
            acc[i][3] += av * b.w;
        }
    }

    const float4* M4 = (const float4*)mask;
    float4* L4 = (float4*)g_L;
#pragma unroll
    for (int i = 0; i < 16; ++i) {
        const int r = m0 + ty * 16 + i;
        float4 mv = M4[(size_t)r * (N_ATAC / 4) + (n0 >> 2) + tx];
        float4 o;
        o.x = acc[i][0] * mv.x;
        o.y = acc[i][1] * mv.y;
        o.z = acc[i][2] * mv.z;
        o.w = acc[i][3] * mv.w;
        L4[((size_t)h * N_RNA + r) * (N_ATAC / 4) + (n0 >> 2) + tx] = o;
        // group-of-4 max for the scan pre-filter
        g_LM[((size_t)h * N_RNA + r) * (N_ATAC / 4) + (n0 >> 2) + tx] =
            fmaxf(fmaxf(o.x, o.y), fmaxf(o.z, o.w));
    }
}

// ---------------- top-k helpers ----------------
__device__ __forceinline__ bool tk_better(float v, int i, float v2, int i2) {
    return (v > v2) || (v == v2 && i < i2);
}

__device__ __forceinline__ void tk_insert(float* bv, int* bi, float v, int gi) {
    bool done = false;
#pragma unroll
    for (int k = 9; k > 0; --k) {
        if (!done) {
            if (tk_better(v, gi, bv[k - 1], bi[k - 1])) {
                bv[k] = bv[k - 1];
                bi[k] = bi[k - 1];
            } else {
                bv[k] = v;
                bi[k] = gi;
                done = true;
            }
        }
    }
    if (!done) { bv[0] = v; bi[0] = gi; }
}

__device__ __forceinline__ float warp_max(float v) {
#pragma unroll
    for (int off = 16; off; off >>= 1)
        v = fmaxf(v, __shfl_xor_sync(0xffffffffu, v, off));
    return v;
}

// ---------------- scan kernel v2: threshold-gated sparse top-10 ----------------
// Warp per (h,r) row. Seed a SAFE threshold (10th largest of 32 lane-maxes of
// group-maxes: >=10 distinct lanes witness an element >= thr, so the true row
// 10th >= thr and a '>=' filter can never drop a top-10 member). Then scan the
// LM array and touch g_L only for groups whose max passes.
__global__ void __launch_bounds__(256) scan_kernel() {
    __shared__ float tvs[8][32][10];
    __shared__ int tis[8][32][10];

    const int t = threadIdx.x;
    const int w = t >> 5;
    const int lane = t & 31;
    const int ridx = blockIdx.x * 8 + w;           // h*4096 + r

    const float4* LM4 = (const float4*)g_LM;
    const float4* L4 = (const float4*)g_L;
    const size_t mbase = (size_t)ridx * (N_ATAC / 16);  // 512 float4 of maxes
    const size_t lbase = (size_t)ridx * (N_ATAC / 4);   // 2048 float4 of logits

    // ---- pass A: lane max over this lane's 16 LM float4s (no inserts) ----
    float lmax = -1e30f;
#pragma unroll 4
    for (int j = 0; j < 16; ++j) {
        float4 v = LM4[mbase + j * 32 + lane];
        lmax = fmaxf(lmax, fmaxf(fmaxf(v.x, v.y), fmaxf(v.z, v.w)));
    }

    // ---- warp-select 10th largest of the 32 lane maxes -> safe thr ----
    float x = lmax;
    float thr = -1e30f;
#pragma unroll
    for (int k = 0; k < 10; ++k) {
        float m = warp_max(x);
        thr = m;
        unsigned b = __ballot_sync(0xffffffffu, x == m);
        int src = __ffs(b) - 1;
        if (lane == src) x = -1e30f;
    }

    // ---- main pass: gated exact top-10 ----
    float bv[10];
    int bi[10];
#pragma unroll
    for (int k = 0; k < 10; ++k) { bv[k] = -1e30f; bi[k] = 0x7fffffff; }

    for (int j = 0; j < 16; ++j) {
        float4 mv = LM4[mbase + j * 32 + lane];
        float thr_eff = fmaxf(thr, bv[9]);
        float mx = fmaxf(fmaxf(mv.x, mv.y), fmaxf(mv.z, mv.w));
        if (mx >= thr_eff) {
            const int gq = j * 32 + lane;          // float4-of-groups index
            float gm[4] = {mv.x, mv.y, mv.z, mv.w};
#pragma unroll
            for (int gg = 0; gg < 4; ++gg) {
                if (gm[gg] >= fmaxf(thr, bv[9])) {
                    const int grp = gq * 4 + gg;   // group of 4 elements
                    float4 lv = L4[lbase + grp];
                    const int a0 = grp * 4;
                    if (tk_better(lv.x, a0, bv[9], bi[9])) tk_insert(bv, bi, lv.x, a0);
                    if (tk_better(lv.y, a0 + 1, bv[9], bi[9])) tk_insert(bv, bi, lv.y, a0 + 1);
                    if (tk_better(lv.z, a0 + 2, bv[9], bi[9])) tk_insert(bv, bi, lv.z, a0 + 2);
                    if (tk_better(lv.w, a0 + 3, bv[9], bi[9])) tk_insert(bv, bi, lv.w, a0 + 3);
                }
            }
        }
        if ((j & 3) == 3) thr = fmaxf(thr, warp_max(bv[9]));  // safe tighten
    }

#pragma unroll
    for (int k = 0; k < 10; ++k) { tvs[w][lane][k] = bv[k]; tis[w][lane][k] = bi[k]; }
    __syncwarp();

    if (lane < 8) {
        float fv[10];
        int fi[10];
#pragma unroll
        for (int k = 0; k < 10; ++k) { fv[k] = -1e30f; fi[k] = 0x7fffffff; }
        for (int s = 0; s < 4; ++s)
            for (int k = 0; k < 10; ++k) {
                float v = tvs[w][lane * 4 + s][k];
                int gi = tis[w][lane * 4 + s][k];
                if (tk_better(v, gi, fv[9], fi[9])) tk_insert(fv, fi, v, gi);
            }
#pragma unroll
        for (int k = 0; k < 10; ++k) { tvs[w][lane][k] = fv[k]; tis[w][lane][k] = fi[k]; }
    }
    __syncwarp();

    if (lane == 0) {
        float fv[10];
        int fi[10];
#pragma unroll
        for (int k = 0; k < 10; ++k) { fv[k] = -1e30f; fi[k] = 0x7fffffff; }
        for (int s = 0; s < 8; ++s)
            for (int k = 0; k < 10; ++k) {
                float v = tvs[w][s][k];
                int gi = tis[w][s][k];
                if (tk_better(v, gi, fv[9], fi[9])) tk_insert(fv, fi, v, gi);
            }
        float sig[10];
#pragma unroll
        for (int k = 0; k < 10; ++k) sig[k] = 1.f / (1.f + expf(-fv[k]));
        float e[10];
        float den = 0.f;
#pragma unroll
        for (int k = 0; k < 10; ++k) { e[k] = expf(sig[k] - sig[0]); den += e[k]; }
        float inv = 1.f / den;
#pragma unroll
        for (int k = 0; k < 10; ++k) {
            float ww = e[k] * inv;
            if (!(sig[k] > THR_S)) ww = 0.f;
            g_W[ridx * 10 + k] = ww;
            g_WI[ridx * 10 + k] = fi[k];
        }
    }
}

// ---------------- aggregation kernel: sparse gather + scatter ----------------
__global__ void __launch_bounds__(256) agg_kernel() {
    const int t = threadIdx.x;
    const int d = t & 63;
    const int q = t >> 6;
    const int ridx = blockIdx.x * 4 + q;
    const int h = ridx >> 12;
    const int r = ridx & 4095;

    float wv[10];
    int wi[10];
#pragma unroll
    for (int k = 0; k < 10; ++k) { wv[k] = g_W[ridx * 10 + k]; wi[k] = g_WI[ridx * 10 + k]; }

    const float vr = g_VR[(size_t)r * 128 + h * 64 + d];
    float accO = 0.f;
#pragma unroll
    for (int k = 0; k < 10; ++k) {
        float w = wv[k];
        int a = wi[k];
        if (w != 0.f) {
            accO += w * g_VA[(size_t)a * 128 + h * 64 + d];
            atomicAdd(&g_AGGA[(size_t)a * 128 + h * 64 + d], w * vr);
        }
    }
    g_AGGR[(size_t)r * 128 + h * 64 + d] = accO;
}

// ---------------- launch ----------------
extern "C" void kernel_launch(void* const* d_in, const int* in_sizes, int n_in,
                              void* d_out, int out_size) {
    const float* x_rna = (const float*)d_in[0];
    const float* x_atac = (const float*)d_in[1];
    const float* chrom_mask = (const float*)d_in[2];
    const float* Wq = (const float*)d_in[3];
    const float* bq = (const float*)d_in[4];
    const float* Wk = (const float*)d_in[5];
    const float* bk = (const float*)d_in[6];
    const float* Wvr = (const float*)d_in[7];
    const float* bvr = (const float*)d_in[8];
    const float* Wva = (const float*)d_in[9];
    const float* bva = (const float*)d_in[10];
    const float* Wor = (const float*)d_in[11];
    const float* bor = (const float*)d_in[12];
    const float* Woa = (const float*)d_in[13];
    const float* boa = (const float*)d_in[14];
    const float* Wsr = (const float*)d_in[15];
    const float* bsr = (const float*)d_in[16];
    const float* Wsa = (const float*)d_in[17];
    const float* bsa = (const float*)d_in[18];
    const float* Wdr = (const float*)d_in[19];
    const float* bdr = (const float*)d_in[20];
    const float* Wda = (const float*)d_in[21];
    const float* bda = (const float*)d_in[22];
    float* out = (float*)d_out;

    float *Qp, *Kp, *VRp, *VAp, *AGGRp, *AGGAp, *CRp, *CAp;
    cudaGetSymbolAddress((void**)&Qp, g_Q);
    cudaGetSymbolAddress((void**)&Kp, g_K);
    cudaGetSymbolAddress((void**)&VRp, g_VR);
    cudaGetSymbolAddress((void**)&VAp, g_VA);
    cudaGetSymbolAddress((void**)&AGGRp, g_AGGR);
    cudaGetSymbolAddress((void**)&AGGAp, g_AGGA);
    cudaGetSymbolAddress((void**)&CRp, g_CR);
    cudaGetSymbolAddress((void**)&CAp, g_CA);

    cudaMemsetAsync(AGGAp, 0, (size_t)N_ATAC * HID * sizeof(float));

    // input projections
    GemmBatch b1 = {};
    b1.op[0] = {x_rna, Wq, bq, Qp, N_RNA, IN_C, 128, 0};
    b1.op[1] = {x_atac, Wk, bk, Kp, N_ATAC, IN_C, 128, 0};
    b1.op[2] = {x_rna, Wvr, bvr, VRp, N_RNA, IN_C, 128, 0};
    b1.op[3] = {x_atac, Wva, bva, VAp, N_ATAC, IN_C, 128, 0};
    b1.op[4] = {x_rna, Wsr, bsr, CRp, N_RNA, IN_C, 256, 128};
    b1.op[5] = {x_atac, Wsa, bsa, CAp, N_ATAC, IN_C, 256, 128};
    gemm_kernel<<<dim3(128, 6), 256>>>(b1);

    // K -> KT
    transpose_k<<<N_ATAC / 64, 256>>>();

    // masked logits GEMM + group maxes
    cudaFuncSetAttribute(logits_kernel, cudaFuncAttributeMaxDynamicSharedMemorySize, 68608);
    logits_kernel<<<dim3(N_ATAC / 128, N_RNA / 128, 2), 256, 68608>>>(chrom_mask);

    // threshold-gated exact top-10 + weights
    scan_kernel<<<2 * N_RNA / 8, 256>>>();

    // sparse aggregation
    agg_kernel<<<2 * N_RNA / 4, 256>>>();

    // out-projections into concat halves
    GemmBatch b2 = {};
    b2.op[0] = {AGGRp, Wor, bor, CRp, N_RNA, HID, 256, 0};
    b2.op[1] = {AGGAp, Woa, boa, CAp, N_ATAC, HID, 256, 0};
    gemm_kernel<<<dim3(128, 2), 256>>>(b2);

    // dim-reduction GEMMs into d_out
    GemmBatch b3 = {};
    b3.op[0] = {CRp, Wdr, bdr, out, N_RNA, 2 * HID, 128, 0};
    b3.op[1] = {CAp, Wda, bda, out + (size_t)N_RNA * HID, N_ATAC, 2 * HID, 128, 0};
    gemm_kernel<<<dim3(128, 2), 256>>>(b3);
}